// round 1
// baseline (speedup 1.0000x reference)
#include <cuda_runtime.h>
#include <math.h>

#define BATCH 2
#define CDIM  96
#define DIN   192
#define NST   16
#define LSEQ  4096
#define NPIX  (BATCH*LSEQ)

// ---------------- persistent device scratch ----------------
__device__ float g_diff [NPIX*CDIM];          // |x-y|
__device__ float g_zs   [NPIX*DIN];           // silu(z)
__device__ float g_xm   [BATCH*DIN*LSEQ];     // in_proj first half, NCHW (conv input)
__device__ float g_x0   [BATCH*DIN*LSEQ];     // conv+silu, row-major seq
__device__ float g_x1   [BATCH*DIN*LSEQ];     // conv+silu, col-major seq
__device__ float g_delta[BATCH*4*DIN*LSEQ];   // softplus(dt) per direction, canonical order
__device__ float g_bc   [BATCH*4*LSEQ*32];    // [B(16) C(16)] per (b,k,l)
__device__ float g_y    [4*BATCH*DIN*LSEQ];   // scan outputs, all at row-major canonical pos

__device__ __forceinline__ float silu_f(float v){ return v / (1.f + __expf(-v)); }

// ================= K1: diff + LN + in_proj GEMM =================
// block: 64 pixels, 256 threads. smem: A[96][64], W[96][128] (3 chunks of 128 outs)
__global__ void k1_prologue(const float* __restrict__ x, const float* __restrict__ y,
                            const float* __restrict__ lnw, const float* __restrict__ lnb,
                            const float* __restrict__ wproj)
{
    extern __shared__ float sm[];
    float* A_s = sm;            // 96*64
    float* W_s = sm + 96*64;    // 96*128
    const int tid = threadIdx.x, lane = tid & 31, warp = tid >> 5;
    const int pix0 = blockIdx.x * 64;

    // phase 1: diff + layernorm into A_s (column-major: A_s[ch*64 + p])
    for (int pp = 0; pp < 8; pp++) {
        const int p = warp * 8 + pp;
        const int base = (pix0 + p) * CDIM;
        float vv[3]; float s = 0.f, s2 = 0.f;
        #pragma unroll
        for (int j = 0; j < 3; j++) {
            int ch = lane + 32 * j;
            float d = fabsf(x[base + ch] - y[base + ch]);
            g_diff[base + ch] = d;
            vv[j] = d; s += d; s2 += d * d;
        }
        #pragma unroll
        for (int o = 16; o > 0; o >>= 1) {
            s  += __shfl_xor_sync(0xffffffffu, s,  o);
            s2 += __shfl_xor_sync(0xffffffffu, s2, o);
        }
        float mu = s * (1.f / 96.f);
        float var = s2 * (1.f / 96.f) - mu * mu;
        float rstd = rsqrtf(var + 1e-5f);
        #pragma unroll
        for (int j = 0; j < 3; j++) {
            int ch = lane + 32 * j;
            A_s[ch * 64 + p] = (vv[j] - mu) * rstd * lnw[ch] + lnb[ch];
        }
    }
    __syncthreads();

    const int pg = tid & 7;       // pixel group: pixels pg*8 .. pg*8+7
    const int og = tid >> 3;      // out group:   outs   og*4 .. og*4+3
    const float4* A4 = (const float4*)A_s;

    for (int oc = 0; oc < 3; oc++) {
        for (int i = tid; i < 96 * 128; i += 256) {
            int kk = i % 96, j = i / 96;
            W_s[kk * 128 + j] = wproj[(oc * 128 + j) * 96 + kk];
        }
        __syncthreads();
        const float4* W4 = (const float4*)W_s;

        float acc[4][8];
        #pragma unroll
        for (int a = 0; a < 4; a++)
            #pragma unroll
            for (int b = 0; b < 8; b++) acc[a][b] = 0.f;

        #pragma unroll 4
        for (int kk = 0; kk < 96; kk++) {
            float4 a0 = A4[kk * 16 + pg * 2];
            float4 a1 = A4[kk * 16 + pg * 2 + 1];
            float4 w  = W4[kk * 32 + og];
            float ws4[4] = {w.x, w.y, w.z, w.w};
            float as8[8] = {a0.x, a0.y, a0.z, a0.w, a1.x, a1.y, a1.z, a1.w};
            #pragma unroll
            for (int jj = 0; jj < 4; jj++)
                #pragma unroll
                for (int pi = 0; pi < 8; pi++)
                    acc[jj][pi] = fmaf(ws4[jj], as8[pi], acc[jj][pi]);
        }

        #pragma unroll
        for (int jj = 0; jj < 4; jj++) {
            int jg = oc * 128 + og * 4 + jj;
            #pragma unroll
            for (int pi = 0; pi < 8; pi++) {
                int pix = pix0 + pg * 8 + pi;
                float v = acc[jj][pi];
                if (jg < DIN) {
                    int b = pix >> 12, l = pix & 4095;
                    g_xm[(size_t)(b * DIN + jg) * LSEQ + l] = v;
                } else {
                    g_zs[(size_t)pix * DIN + (jg - DIN)] = silu_f(v);
                }
            }
        }
        __syncthreads();
    }
}

// ================= K2: depthwise 3x3 conv + silu, dual store =================
__global__ void k2_conv(const float* __restrict__ cw, const float* __restrict__ cb)
{
    int idx = blockIdx.x * 256 + threadIdx.x;          // < 2*192*4096
    int w_ = idx & 63, h_ = (idx >> 6) & 63;
    int t  = idx >> 12;
    int d  = t % DIN, b = t / DIN;
    const float* src = g_xm + (size_t)(b * DIN + d) * LSEQ;
    float acc = cb[d];
    #pragma unroll
    for (int dy = 0; dy < 3; dy++) {
        int hh = h_ + dy - 1;
        if (hh < 0 || hh > 63) continue;
        #pragma unroll
        for (int dx = 0; dx < 3; dx++) {
            int ww = w_ + dx - 1;
            if (ww < 0 || ww > 63) continue;
            acc = fmaf(src[hh * 64 + ww], cw[d * 9 + dy * 3 + dx], acc);
        }
    }
    float v = silu_f(acc);
    g_x0[idx] = v;
    g_x1[(size_t)(b * DIN + d) * LSEQ + w_ * 64 + h_] = v;
}

// ================= K3: x_proj + dt_proj + softplus =================
// block: one (b,k), 64 positions; 256 threads
__global__ void k3_xproj(const float* __restrict__ xpw, const float* __restrict__ dtw,
                         const float* __restrict__ dtb)
{
    extern __shared__ float sm[];
    float* u_s  = sm;                         // 192*64
    float* wp_s = u_s + 192 * 64;             // 38*192
    float* xd_s = wp_s + 38 * 192;            // 38*65 (padded)
    float* dw_s = xd_s + 38 * 65;             // 192*6
    const int tid = threadIdx.x;
    const int bk = blockIdx.x >> 6;
    const int b = bk >> 2, k = bk & 3;
    const int l0 = (blockIdx.x & 63) << 6;
    const float* seq = (k & 1) ? g_x1 : g_x0;

    for (int i = tid; i < 192 * 64; i += 256) {
        int d = i >> 6, c = i & 63;
        u_s[i] = seq[(size_t)(b * DIN + d) * LSEQ + l0 + c];
    }
    for (int i = tid; i < 38 * 192; i += 256) wp_s[i] = xpw[k * 38 * 192 + i];
    for (int i = tid; i < 192 * 6;  i += 256) dw_s[i] = dtw[k * 192 * 6 + i];
    __syncthreads();

    const int col = tid & 63, grp = tid >> 6;
    float acc[10];
    #pragma unroll
    for (int j = 0; j < 10; j++) acc[j] = 0.f;
    for (int kk = 0; kk < 192; kk++) {
        float uv = u_s[kk * 64 + col];
        #pragma unroll
        for (int j = 0; j < 10; j++) {
            int row = grp + 4 * j;
            if (row < 38) acc[j] = fmaf(wp_s[row * 192 + kk], uv, acc[j]);
        }
    }
    #pragma unroll
    for (int j = 0; j < 10; j++) {
        int row = grp + 4 * j;
        if (row < 38) xd_s[row * 65 + col] = acc[j];
    }
    __syncthreads();

    // B,C -> g_bc  (rows 6..37)
    const size_t bcbase = (size_t)(b * 4 + k) * LSEQ + l0;
    for (int i = tid; i < 32 * 64; i += 256) {
        int n = i & 31, cc = i >> 5;
        g_bc[(bcbase + cc) * 32 + n] = xd_s[(6 + n) * 65 + cc];
    }
    // delta = softplus(dt_w @ dts + dt_b)  (rows 0..5)
    const int dg = tid >> 6;
    const size_t dbase = (size_t)(b * 4 + k) * DIN * LSEQ;
    for (int j = 0; j < 48; j++) {
        int d = dg + 4 * j;
        float val = dtb[k * DIN + d];
        #pragma unroll
        for (int r = 0; r < 6; r++)
            val = fmaf(dw_s[d * 6 + r], xd_s[r * 65 + col], val);
        val = fmaxf(val, 0.f) + log1pf(__expf(-fabsf(val)));   // stable softplus
        g_delta[dbase + (size_t)d * LSEQ + l0 + col] = val;
    }
}

// ================= K4: selective scan (warp per (b,k,d)) =================
__global__ void k4_scan(const float* __restrict__ alog, const float* __restrict__ ds)
{
    const int tid = threadIdx.x, lane = tid & 31;
    const int wg = blockIdx.x * 8 + (tid >> 5);       // 0..1535
    const int d = wg % DIN;
    const int k = (wg / DIN) & 3;
    const int b = wg / (DIN * 4);

    float A_n = 0.f;
    if (lane < 16) A_n = -__expf(alog[(k * DIN + d) * NST + lane]);
    const float Dd = ds[k * DIN + d];

    const float* dptr = g_delta + ((size_t)(b * 4 + k) * DIN + d) * LSEQ;
    const float* uptr = ((k & 1) ? g_x1 : g_x0) + ((size_t)b * DIN + d) * LSEQ;
    const float* bcp  = g_bc + (size_t)(b * 4 + k) * LSEQ * 32;
    float* yp = g_y + ((size_t)(k * BATCH + b) * DIN + d) * LSEQ;

    const bool rev = (k >= 2);
    const bool tr  = (k & 1);
    float h = 0.f;

    for (int i = 0; i < LSEQ; i++) {
        const int l = rev ? (LSEQ - 1 - i) : i;
        float bc  = __ldg(bcp + (size_t)l * 32 + lane);
        float del = __ldg(dptr + l);
        float u   = __ldg(uptr + l);
        float cv  = __shfl_xor_sync(0xffffffffu, bc, 16);   // C_n to lanes 0..15
        float a   = __expf(del * A_n);
        h = fmaf(a, h, del * u * bc);
        float t = (lane < 16) ? h * cv : 0.f;
        t += __shfl_xor_sync(0xffffffffu, t, 8);
        t += __shfl_xor_sync(0xffffffffu, t, 4);
        t += __shfl_xor_sync(0xffffffffu, t, 2);
        t += __shfl_xor_sync(0xffffffffu, t, 1);
        if (lane == 0) {
            int lr = tr ? ((l & 63) * 64 + (l >> 6)) : l;   // fold transpose into store
            yp[lr] = t + Dd * u;
        }
    }
}

// ================= K5: merge + out-LN + silu(z) gate + out_proj + residual =================
// block: 32 pixels (consecutive row-major l), 256 threads
__global__ void k5_final(const float* __restrict__ onw, const float* __restrict__ onb,
                         const float* __restrict__ wout, float* __restrict__ out)
{
    extern __shared__ float sm[];
    float* yc = sm;                  // 192*36 (padded, 16B-aligned rows)
    float* ws = sm + 192 * 36;       // 96*192
    const int tid = threadIdx.x, lane = tid & 31, warp = tid >> 5;
    const int b = blockIdx.x >> 7;
    const int l0 = (blockIdx.x & 127) << 5;

    for (int i = tid; i < 192 * 32; i += 256) {
        int d = i >> 5, p = i & 31;
        size_t off = (size_t)d * LSEQ + l0 + p;
        float v = g_y[((size_t)(0 * BATCH + b) * DIN) * LSEQ + off]
                + g_y[((size_t)(1 * BATCH + b) * DIN) * LSEQ + off]
                + g_y[((size_t)(2 * BATCH + b) * DIN) * LSEQ + off]
                + g_y[((size_t)(3 * BATCH + b) * DIN) * LSEQ + off];
        yc[d * 36 + p] = v;
    }
    for (int i = tid; i < 96 * 192; i += 256) ws[i] = wout[i];
    __syncthreads();

    // layernorm over 192 + gate by silu(z); warp handles 4 pixels
    #pragma unroll
    for (int pp = 0; pp < 4; pp++) {
        const int p = warp * 4 + pp;
        float s = 0.f, s2 = 0.f, vv[6];
        #pragma unroll
        for (int j = 0; j < 6; j++) {
            float v = yc[(lane + 32 * j) * 36 + p];
            vv[j] = v; s += v; s2 += v * v;
        }
        #pragma unroll
        for (int o = 16; o > 0; o >>= 1) {
            s  += __shfl_xor_sync(0xffffffffu, s,  o);
            s2 += __shfl_xor_sync(0xffffffffu, s2, o);
        }
        float mu = s * (1.f / 192.f);
        float var = s2 * (1.f / 192.f) - mu * mu;
        float rstd = rsqrtf(var + 1e-5f);
        size_t zbase = ((size_t)(b * LSEQ + l0 + p)) * DIN;
        #pragma unroll
        for (int j = 0; j < 6; j++) {
            int dd = lane + 32 * j;
            float g = (vv[j] - mu) * rstd * onw[dd] + onb[dd];
            yc[dd * 36 + p] = g * g_zs[zbase + dd];
        }
    }
    __syncthreads();

    // out_proj 192->96 + residual
    const int og = tid >> 3;   // 0..31 -> outs og*3..+2
    const int pg = tid & 7;    // pixels pg*4..+3
    float acc[3][4];
    #pragma unroll
    for (int a = 0; a < 3; a++)
        #pragma unroll
        for (int c = 0; c < 4; c++) acc[a][c] = 0.f;

    #pragma unroll 4
    for (int dd = 0; dd < 192; dd++) {
        float4 gv = *(const float4*)&yc[dd * 36 + pg * 4];
        float g4[4] = {gv.x, gv.y, gv.z, gv.w};
        #pragma unroll
        for (int oi = 0; oi < 3; oi++) {
            float w = ws[(og * 3 + oi) * 192 + dd];
            #pragma unroll
            for (int pi = 0; pi < 4; pi++)
                acc[oi][pi] = fmaf(w, g4[pi], acc[oi][pi]);
        }
    }
    #pragma unroll
    for (int oi = 0; oi < 3; oi++)
        #pragma unroll
        for (int pi = 0; pi < 4; pi++) {
            int o = og * 3 + oi;
            size_t pix = (size_t)b * LSEQ + l0 + pg * 4 + pi;
            out[pix * 96 + o] = g_diff[pix * 96 + o] + acc[oi][pi];
        }
}

// ================= launch =================
extern "C" void kernel_launch(void* const* d_in, const int* in_sizes, int n_in,
                              void* d_out, int out_size)
{
    const float* x     = (const float*)d_in[0];
    const float* y     = (const float*)d_in[1];
    const float* ln_w  = (const float*)d_in[2];
    const float* ln_b  = (const float*)d_in[3];
    const float* ipw   = (const float*)d_in[4];
    const float* cw    = (const float*)d_in[5];
    const float* cb    = (const float*)d_in[6];
    const float* xpw   = (const float*)d_in[7];
    const float* dtw   = (const float*)d_in[8];
    const float* dtb   = (const float*)d_in[9];
    const float* alog  = (const float*)d_in[10];
    const float* ds    = (const float*)d_in[11];
    const float* onw   = (const float*)d_in[12];
    const float* onb   = (const float*)d_in[13];
    const float* wout  = (const float*)d_in[14];
    float* out = (float*)d_out;

    const int smem1 = (96 * 64 + 96 * 128) * 4;                       // 73728
    const int smem3 = (192 * 64 + 38 * 192 + 38 * 65 + 192 * 6) * 4; // 92824
    const int smem5 = (192 * 36 + 96 * 192) * 4;                      // 101376
    cudaFuncSetAttribute(k1_prologue, cudaFuncAttributeMaxDynamicSharedMemorySize, smem1);
    cudaFuncSetAttribute(k3_xproj,   cudaFuncAttributeMaxDynamicSharedMemorySize, smem3);
    cudaFuncSetAttribute(k5_final,   cudaFuncAttributeMaxDynamicSharedMemorySize, smem5);

    k1_prologue<<<128, 256, smem1>>>(x, y, ln_w, ln_b, ipw);
    k2_conv<<<(BATCH * DIN * LSEQ) / 256, 256>>>(cw, cb);
    k3_xproj<<<BATCH * 4 * (LSEQ / 64), 256, smem3>>>(xpw, dtw, dtb);
    k4_scan<<<(BATCH * 4 * DIN) / 8, 256>>>(alog, ds);
    k5_final<<<BATCH * (LSEQ / 32), 256, smem5>>>(onw, onb, wout, out);
}

// round 2
// speedup vs baseline: 1.3362x; 1.3362x over previous
#include <cuda_runtime.h>
#include <math.h>

#define BATCH 2
#define CDIM  96
#define DIN   192
#define NST   16
#define LSEQ  4096
#define NPIX  (BATCH*LSEQ)
#define NCH   (BATCH*4*DIN)     // 1536 scan channels
#define NCHUNK 8
#define CLEN  (LSEQ/NCHUNK)     // 512

// ---------------- persistent device scratch ----------------
__device__ float g_diff [NPIX*CDIM];          // |x-y|
__device__ float g_zs   [NPIX*DIN];           // silu(z)
__device__ float g_xm   [BATCH*DIN*LSEQ];     // in_proj first half, NCHW (conv input)
__device__ float g_x0   [BATCH*DIN*LSEQ];     // conv+silu, row-major seq
__device__ float g_x1   [BATCH*DIN*LSEQ];     // conv+silu, col-major seq
__device__ float g_delta[BATCH*4*DIN*LSEQ];   // softplus(dt) per direction
__device__ float g_bc   [BATCH*4*LSEQ*32];    // [B(16) C(16)] per (b,k,l)
__device__ float g_y    [4*BATCH*DIN*LSEQ];   // scan outputs at row-major canonical pos
__device__ float g_P    [NCH*NCHUNK*NST];     // per-chunk decay product
__device__ float g_he   [NCH*NCHUNK*NST];     // per-chunk local end state
__device__ float g_H    [NCH*NCHUNK*NST];     // per-chunk start state (carry)

__device__ __forceinline__ float silu_f(float v){ return v / (1.f + __expf(-v)); }

// ================= K1: diff + LN + in_proj GEMM =================
// grid (128, 3): blockIdx.x = 64-pixel tile, blockIdx.y = 128-output chunk
__global__ void k1_prologue(const float* __restrict__ x, const float* __restrict__ y,
                            const float* __restrict__ lnw, const float* __restrict__ lnb,
                            const float* __restrict__ wproj)
{
    extern __shared__ float sm[];
    float* A_s = sm;            // 96*64
    float* W_s = sm + 96*64;    // 96*128
    const int tid = threadIdx.x, lane = tid & 31, warp = tid >> 5;
    const int pix0 = blockIdx.x * 64;
    const int oc = blockIdx.y;

    // phase 1: diff + layernorm into A_s (column-major: A_s[ch*64 + p])
    for (int pp = 0; pp < 8; pp++) {
        const int p = warp * 8 + pp;
        const int base = (pix0 + p) * CDIM;
        float vv[3]; float s = 0.f, s2 = 0.f;
        #pragma unroll
        for (int j = 0; j < 3; j++) {
            int ch = lane + 32 * j;
            float d = fabsf(x[base + ch] - y[base + ch]);
            if (oc == 0) g_diff[base + ch] = d;
            vv[j] = d; s += d; s2 += d * d;
        }
        #pragma unroll
        for (int o = 16; o > 0; o >>= 1) {
            s  += __shfl_xor_sync(0xffffffffu, s,  o);
            s2 += __shfl_xor_sync(0xffffffffu, s2, o);
        }
        float mu = s * (1.f / 96.f);
        float var = s2 * (1.f / 96.f) - mu * mu;
        float rstd = rsqrtf(var + 1e-5f);
        #pragma unroll
        for (int j = 0; j < 3; j++) {
            int ch = lane + 32 * j;
            A_s[ch * 64 + p] = (vv[j] - mu) * rstd * lnw[ch] + lnb[ch];
        }
    }
    for (int i = tid; i < 96 * 128; i += 256) {
        int kk = i % 96, j = i / 96;
        W_s[kk * 128 + j] = wproj[(oc * 128 + j) * 96 + kk];
    }
    __syncthreads();

    const int pg = tid & 7;       // pixels pg*8 .. pg*8+7
    const int og = tid >> 3;      // outs   og*4 .. og*4+3
    const float4* A4 = (const float4*)A_s;
    const float4* W4 = (const float4*)W_s;

    float acc[4][8];
    #pragma unroll
    for (int a = 0; a < 4; a++)
        #pragma unroll
        for (int b = 0; b < 8; b++) acc[a][b] = 0.f;

    #pragma unroll 4
    for (int kk = 0; kk < 96; kk++) {
        float4 a0 = A4[kk * 16 + pg * 2];
        float4 a1 = A4[kk * 16 + pg * 2 + 1];
        float4 w  = W4[kk * 32 + og];
        float ws4[4] = {w.x, w.y, w.z, w.w};
        float as8[8] = {a0.x, a0.y, a0.z, a0.w, a1.x, a1.y, a1.z, a1.w};
        #pragma unroll
        for (int jj = 0; jj < 4; jj++)
            #pragma unroll
            for (int pi = 0; pi < 8; pi++)
                acc[jj][pi] = fmaf(ws4[jj], as8[pi], acc[jj][pi]);
    }

    #pragma unroll
    for (int jj = 0; jj < 4; jj++) {
        int jg = oc * 128 + og * 4 + jj;
        #pragma unroll
        for (int pi = 0; pi < 8; pi++) {
            int pix = pix0 + pg * 8 + pi;
            float v = acc[jj][pi];
            if (jg < DIN) {
                int b = pix >> 12, l = pix & 4095;
                g_xm[(size_t)(b * DIN + jg) * LSEQ + l] = v;
            } else {
                g_zs[(size_t)pix * DIN + (jg - DIN)] = silu_f(v);
            }
        }
    }
}

// ================= K2: depthwise 3x3 conv + silu, dual store =================
__global__ void k2_conv(const float* __restrict__ cw, const float* __restrict__ cb)
{
    int idx = blockIdx.x * 256 + threadIdx.x;
    int w_ = idx & 63, h_ = (idx >> 6) & 63;
    int t  = idx >> 12;
    int d  = t % DIN, b = t / DIN;
    const float* src = g_xm + (size_t)(b * DIN + d) * LSEQ;
    float acc = cb[d];
    #pragma unroll
    for (int dy = 0; dy < 3; dy++) {
        int hh = h_ + dy - 1;
        if (hh < 0 || hh > 63) continue;
        #pragma unroll
        for (int dx = 0; dx < 3; dx++) {
            int ww = w_ + dx - 1;
            if (ww < 0 || ww > 63) continue;
            acc = fmaf(src[hh * 64 + ww], cw[d * 9 + dy * 3 + dx], acc);
        }
    }
    float v = silu_f(acc);
    g_x0[idx] = v;
    g_x1[(size_t)(b * DIN + d) * LSEQ + w_ * 64 + h_] = v;
}

// ================= K3: x_proj + dt_proj + softplus =================
__global__ void k3_xproj(const float* __restrict__ xpw, const float* __restrict__ dtw,
                         const float* __restrict__ dtb)
{
    extern __shared__ float sm[];
    float* u_s  = sm;                         // 192*64
    float* wp_s = u_s + 192 * 64;             // 38*192
    float* xd_s = wp_s + 38 * 192;            // 38*65 (padded)
    float* dw_s = xd_s + 38 * 65;             // 192*6
    const int tid = threadIdx.x;
    const int bk = blockIdx.x >> 6;
    const int b = bk >> 2, k = bk & 3;
    const int l0 = (blockIdx.x & 63) << 6;
    const float* seq = (k & 1) ? g_x1 : g_x0;

    for (int i = tid; i < 192 * 64; i += 256) {
        int d = i >> 6, c = i & 63;
        u_s[i] = seq[(size_t)(b * DIN + d) * LSEQ + l0 + c];
    }
    for (int i = tid; i < 38 * 192; i += 256) wp_s[i] = xpw[k * 38 * 192 + i];
    for (int i = tid; i < 192 * 6;  i += 256) dw_s[i] = dtw[k * 192 * 6 + i];
    __syncthreads();

    const int col = tid & 63, grp = tid >> 6;
    float acc[10];
    #pragma unroll
    for (int j = 0; j < 10; j++) acc[j] = 0.f;
    for (int kk = 0; kk < 192; kk++) {
        float uv = u_s[kk * 64 + col];
        #pragma unroll
        for (int j = 0; j < 10; j++) {
            int row = grp + 4 * j;
            if (row < 38) acc[j] = fmaf(wp_s[row * 192 + kk], uv, acc[j]);
        }
    }
    #pragma unroll
    for (int j = 0; j < 10; j++) {
        int row = grp + 4 * j;
        if (row < 38) xd_s[row * 65 + col] = acc[j];
    }
    __syncthreads();

    const size_t bcbase = (size_t)(b * 4 + k) * LSEQ + l0;
    for (int i = tid; i < 32 * 64; i += 256) {
        int n = i & 31, cc = i >> 5;
        g_bc[(bcbase + cc) * 32 + n] = xd_s[(6 + n) * 65 + cc];
    }
    const int dg = tid >> 6;
    const size_t dbase = (size_t)(b * 4 + k) * DIN * LSEQ;
    for (int j = 0; j < 48; j++) {
        int d = dg + 4 * j;
        float val = dtb[k * DIN + d];
        #pragma unroll
        for (int r = 0; r < 6; r++)
            val = fmaf(dw_s[d * 6 + r], xd_s[r * 65 + col], val);
        val = fmaxf(val, 0.f) + log1pf(__expf(-fabsf(val)));
        g_delta[dbase + (size_t)d * LSEQ + l0 + col] = val;
    }
}

// ================= K4a: chunked scan pass A (local state + decay product) ==========
// warp = (pair, chunk); lanes 0-15 -> channel 2*pair, lanes 16-31 -> 2*pair+1
__global__ void k4a_local(const float* __restrict__ alog)
{
    const int lane = threadIdx.x & 31;
    const int w = blockIdx.x * 8 + (threadIdx.x >> 5);   // 0..6143
    const int pair = w >> 3, chunk = w & 7;
    const int half = lane >> 4, n = lane & 15;
    const int ch = pair * 2 + half;
    const int d = ch % DIN, bk = ch / DIN;
    const int k = bk & 3, b = bk >> 2;
    const float An2 = -__expf(alog[(k * DIN + d) * NST + n]) * 1.44269504f;
    const bool rev = (k >= 2);

    const float* dptr = g_delta + ((size_t)bk * DIN + d) * LSEQ;
    const float* uptr = ((k & 1) ? g_x1 : g_x0) + ((size_t)b * DIN + d) * LSEQ;
    const float* bcp  = g_bc + (size_t)bk * LSEQ * 32;
    const int i0 = chunk * CLEN;

    float h = 0.f, P = 1.f;
    for (int ii = 0; ii < CLEN; ii += 4) {
        const int lb = rev ? (LSEQ - 1 - (i0 + ii + 3)) : (i0 + ii);
        float4 d4 = *(const float4*)(dptr + lb);
        float4 u4 = *(const float4*)(uptr + lb);
        float dd[4] = {d4.x, d4.y, d4.z, d4.w};
        float uu[4] = {u4.x, u4.y, u4.z, u4.w};
        #pragma unroll
        for (int j = 0; j < 4; j++) {
            const int jj = rev ? 3 - j : j;
            const int l = lb + jj;
            float v = bcp[(size_t)l * 32 + lane];
            float o = __shfl_xor_sync(0xffffffffu, v, 16);
            float Bv = half ? o : v;
            float a = exp2f(dd[jj] * An2);
            h = fmaf(a, h, dd[jj] * uu[jj] * Bv);
            P *= a;
        }
    }
    g_P [(ch * NCHUNK + chunk) * NST + n] = P;
    g_he[(ch * NCHUNK + chunk) * NST + n] = h;
}

// ================= K4b: carry across chunks =================
__global__ void k4b_carry()
{
    int idx = blockIdx.x * 256 + threadIdx.x;   // 0..24575
    int ch = idx >> 4, n = idx & 15;
    float H = 0.f;
    #pragma unroll
    for (int c = 0; c < NCHUNK; c++) {
        int o = (ch * NCHUNK + c) * NST + n;
        g_H[o] = H;
        H = g_P[o] * H + g_he[o];
    }
}

// ================= K4c: chunked scan pass C (seeded, emit y) =================
__global__ void k4c_emit(const float* __restrict__ alog, const float* __restrict__ ds)
{
    const int lane = threadIdx.x & 31;
    const int w = blockIdx.x * 8 + (threadIdx.x >> 5);
    const int pair = w >> 3, chunk = w & 7;
    const int half = lane >> 4, n = lane & 15;
    const int ch = pair * 2 + half;
    const int d = ch % DIN, bk = ch / DIN;
    const int k = bk & 3, b = bk >> 2;
    const float An2 = -__expf(alog[(k * DIN + d) * NST + n]) * 1.44269504f;
    const bool rev = (k >= 2);
    const bool tr  = (k & 1);
    const float Dd = ds[k * DIN + d];

    const float* dptr = g_delta + ((size_t)bk * DIN + d) * LSEQ;
    const float* uptr = ((k & 1) ? g_x1 : g_x0) + ((size_t)b * DIN + d) * LSEQ;
    const float* bcp  = g_bc + (size_t)bk * LSEQ * 32;
    float* yp = g_y + ((size_t)(k * BATCH + b) * DIN + d) * LSEQ;
    const int i0 = chunk * CLEN;

    float h = g_H[(ch * NCHUNK + chunk) * NST + n];

    for (int ii = 0; ii < CLEN; ii += 4) {
        const int lb = rev ? (LSEQ - 1 - (i0 + ii + 3)) : (i0 + ii);
        float4 d4 = *(const float4*)(dptr + lb);
        float4 u4 = *(const float4*)(uptr + lb);
        float dd[4] = {d4.x, d4.y, d4.z, d4.w};
        float uu[4] = {u4.x, u4.y, u4.z, u4.w};
        #pragma unroll
        for (int j = 0; j < 4; j++) {
            const int jj = rev ? 3 - j : j;
            const int l = lb + jj;
            float v = bcp[(size_t)l * 32 + lane];
            float o = __shfl_xor_sync(0xffffffffu, v, 16);
            float Bv = half ? o : v;
            float Cv = half ? v : o;
            float a = exp2f(dd[jj] * An2);
            h = fmaf(a, h, dd[jj] * uu[jj] * Bv);
            float t = h * Cv;
            t += __shfl_xor_sync(0xffffffffu, t, 8);
            t += __shfl_xor_sync(0xffffffffu, t, 4);
            t += __shfl_xor_sync(0xffffffffu, t, 2);
            t += __shfl_xor_sync(0xffffffffu, t, 1);
            if (n == 0) {
                int lr = tr ? ((l & 63) * 64 + (l >> 6)) : l;
                yp[lr] = t + Dd * uu[jj];
            }
        }
    }
}

// ================= K5: merge + out-LN + silu(z) gate + out_proj + residual ========
__global__ void k5_final(const float* __restrict__ onw, const float* __restrict__ onb,
                         const float* __restrict__ wout, float* __restrict__ out)
{
    extern __shared__ float sm[];
    float* yc = sm;                  // 192*36
    float* ws = sm + 192 * 36;       // 96*192
    const int tid = threadIdx.x, lane = tid & 31, warp = tid >> 5;
    const int b = blockIdx.x >> 7;
    const int l0 = (blockIdx.x & 127) << 5;

    for (int i = tid; i < 192 * 32; i += 256) {
        int d = i >> 5, p = i & 31;
        size_t off = (size_t)d * LSEQ + l0 + p;
        float v = g_y[((size_t)(0 * BATCH + b) * DIN) * LSEQ + off]
                + g_y[((size_t)(1 * BATCH + b) * DIN) * LSEQ + off]
                + g_y[((size_t)(2 * BATCH + b) * DIN) * LSEQ + off]
                + g_y[((size_t)(3 * BATCH + b) * DIN) * LSEQ + off];
        yc[d * 36 + p] = v;
    }
    for (int i = tid; i < 96 * 192; i += 256) ws[i] = wout[i];
    __syncthreads();

    #pragma unroll
    for (int pp = 0; pp < 4; pp++) {
        const int p = warp * 4 + pp;
        float s = 0.f, s2 = 0.f, vv[6];
        #pragma unroll
        for (int j = 0; j < 6; j++) {
            float v = yc[(lane + 32 * j) * 36 + p];
            vv[j] = v; s += v; s2 += v * v;
        }
        #pragma unroll
        for (int o = 16; o > 0; o >>= 1) {
            s  += __shfl_xor_sync(0xffffffffu, s,  o);
            s2 += __shfl_xor_sync(0xffffffffu, s2, o);
        }
        float mu = s * (1.f / 192.f);
        float var = s2 * (1.f / 192.f) - mu * mu;
        float rstd = rsqrtf(var + 1e-5f);
        size_t zbase = ((size_t)(b * LSEQ + l0 + p)) * DIN;
        #pragma unroll
        for (int j = 0; j < 6; j++) {
            int dd = lane + 32 * j;
            float g = (vv[j] - mu) * rstd * onw[dd] + onb[dd];
            yc[dd * 36 + p] = g * g_zs[zbase + dd];
        }
    }
    __syncthreads();

    const int og = tid >> 3;
    const int pg = tid & 7;
    float acc[3][4];
    #pragma unroll
    for (int a = 0; a < 3; a++)
        #pragma unroll
        for (int c = 0; c < 4; c++) acc[a][c] = 0.f;

    #pragma unroll 4
    for (int dd = 0; dd < 192; dd++) {
        float4 gv = *(const float4*)&yc[dd * 36 + pg * 4];
        float g4[4] = {gv.x, gv.y, gv.z, gv.w};
        #pragma unroll
        for (int oi = 0; oi < 3; oi++) {
            float w2 = ws[(og * 3 + oi) * 192 + dd];
            #pragma unroll
            for (int pi = 0; pi < 4; pi++)
                acc[oi][pi] = fmaf(w2, g4[pi], acc[oi][pi]);
        }
    }
    #pragma unroll
    for (int oi = 0; oi < 3; oi++)
        #pragma unroll
        for (int pi = 0; pi < 4; pi++) {
            int o = og * 3 + oi;
            size_t pix = (size_t)b * LSEQ + l0 + pg * 4 + pi;
            out[pix * 96 + o] = g_diff[pix * 96 + o] + acc[oi][pi];
        }
}

// ================= launch =================
extern "C" void kernel_launch(void* const* d_in, const int* in_sizes, int n_in,
                              void* d_out, int out_size)
{
    const float* x     = (const float*)d_in[0];
    const float* y     = (const float*)d_in[1];
    const float* ln_w  = (const float*)d_in[2];
    const float* ln_b  = (const float*)d_in[3];
    const float* ipw   = (const float*)d_in[4];
    const float* cw    = (const float*)d_in[5];
    const float* cb    = (const float*)d_in[6];
    const float* xpw   = (const float*)d_in[7];
    const float* dtw   = (const float*)d_in[8];
    const float* dtb   = (const float*)d_in[9];
    const float* alog  = (const float*)d_in[10];
    const float* ds    = (const float*)d_in[11];
    const float* onw   = (const float*)d_in[12];
    const float* onb   = (const float*)d_in[13];
    const float* wout  = (const float*)d_in[14];
    float* out = (float*)d_out;

    const int smem1 = (96 * 64 + 96 * 128) * 4;
    const int smem3 = (192 * 64 + 38 * 192 + 38 * 65 + 192 * 6) * 4;
    const int smem5 = (192 * 36 + 96 * 192) * 4;
    cudaFuncSetAttribute(k1_prologue, cudaFuncAttributeMaxDynamicSharedMemorySize, smem1);
    cudaFuncSetAttribute(k3_xproj,   cudaFuncAttributeMaxDynamicSharedMemorySize, smem3);
    cudaFuncSetAttribute(k5_final,   cudaFuncAttributeMaxDynamicSharedMemorySize, smem5);

    k1_prologue<<<dim3(128, 3), 256, smem1>>>(x, y, ln_w, ln_b, ipw);
    k2_conv<<<(BATCH * DIN * LSEQ) / 256, 256>>>(cw, cb);
    k3_xproj<<<BATCH * 4 * (LSEQ / 64), 256, smem3>>>(xpw, dtw, dtb);
    k4a_local<<<(NCH / 2) * NCHUNK / 8, 256>>>(alog);
    k4b_carry<<<NCH * NST / 256, 256>>>();
    k4c_emit<<<(NCH / 2) * NCHUNK / 8, 256>>>(alog, ds);
    k5_final<<<BATCH * (LSEQ / 32), 256, smem5>>>(onw, onb, wout, out);
}

// round 3
// speedup vs baseline: 2.3985x; 1.7950x over previous
#include <cuda_runtime.h>
#include <math.h>

#define BATCH 2
#define CDIM  96
#define DIN   192
#define NST   16
#define LSEQ  4096
#define NPIX  (BATCH*LSEQ)
#define NCH   (BATCH*4*DIN)     // 1536 scan channels
#define NCHUNK 16
#define CLEN  (LSEQ/NCHUNK)     // 256

// ---------------- persistent device scratch ----------------
__device__ float g_diff [NPIX*CDIM];
__device__ float g_zs   [NPIX*DIN];
__device__ float g_xm   [BATCH*DIN*LSEQ];
__device__ float g_x0   [BATCH*DIN*LSEQ];
__device__ float g_x1   [BATCH*DIN*LSEQ];
__device__ float g_delta[BATCH*4*DIN*LSEQ];
__device__ float g_bc   [BATCH*4*LSEQ*32];
__device__ float g_y    [4*BATCH*DIN*LSEQ];
__device__ float g_P    [NCH*NCHUNK*NST];
__device__ float g_he   [NCH*NCHUNK*NST];
__device__ float g_H    [NCH*NCHUNK*NST];

__device__ __forceinline__ float silu_f(float v){ return v / (1.f + __expf(-v)); }

// ================= K1: diff + LN + in_proj GEMM =================
__global__ void k1_prologue(const float* __restrict__ x, const float* __restrict__ y,
                            const float* __restrict__ lnw, const float* __restrict__ lnb,
                            const float* __restrict__ wproj)
{
    extern __shared__ float sm[];
    float* A_s = sm;            // 96*64
    float* W_s = sm + 96*64;    // 96*128
    const int tid = threadIdx.x, lane = tid & 31, warp = tid >> 5;
    const int pix0 = blockIdx.x * 64;
    const int oc = blockIdx.y;

    for (int pp = 0; pp < 8; pp++) {
        const int p = warp * 8 + pp;
        const int base = (pix0 + p) * CDIM;
        float vv[3]; float s = 0.f, s2 = 0.f;
        #pragma unroll
        for (int j = 0; j < 3; j++) {
            int ch = lane + 32 * j;
            float d = fabsf(x[base + ch] - y[base + ch]);
            if (oc == 0) g_diff[base + ch] = d;
            vv[j] = d; s += d; s2 += d * d;
        }
        #pragma unroll
        for (int o = 16; o > 0; o >>= 1) {
            s  += __shfl_xor_sync(0xffffffffu, s,  o);
            s2 += __shfl_xor_sync(0xffffffffu, s2, o);
        }
        float mu = s * (1.f / 96.f);
        float var = s2 * (1.f / 96.f) - mu * mu;
        float rstd = rsqrtf(var + 1e-5f);
        #pragma unroll
        for (int j = 0; j < 3; j++) {
            int ch = lane + 32 * j;
            A_s[ch * 64 + p] = (vv[j] - mu) * rstd * lnw[ch] + lnb[ch];
        }
    }
    for (int i = tid; i < 96 * 128; i += 256) {
        int kk = i % 96, j = i / 96;
        W_s[kk * 128 + j] = wproj[(oc * 128 + j) * 96 + kk];
    }
    __syncthreads();

    const int pg = tid & 7;
    const int og = tid >> 3;
    const float4* A4 = (const float4*)A_s;
    const float4* W4 = (const float4*)W_s;

    float acc[4][8];
    #pragma unroll
    for (int a = 0; a < 4; a++)
        #pragma unroll
        for (int b = 0; b < 8; b++) acc[a][b] = 0.f;

    #pragma unroll 4
    for (int kk = 0; kk < 96; kk++) {
        float4 a0 = A4[kk * 16 + pg * 2];
        float4 a1 = A4[kk * 16 + pg * 2 + 1];
        float4 w  = W4[kk * 32 + og];
        float ws4[4] = {w.x, w.y, w.z, w.w};
        float as8[8] = {a0.x, a0.y, a0.z, a0.w, a1.x, a1.y, a1.z, a1.w};
        #pragma unroll
        for (int jj = 0; jj < 4; jj++)
            #pragma unroll
            for (int pi = 0; pi < 8; pi++)
                acc[jj][pi] = fmaf(ws4[jj], as8[pi], acc[jj][pi]);
    }

    #pragma unroll
    for (int jj = 0; jj < 4; jj++) {
        int jg = oc * 128 + og * 4 + jj;
        #pragma unroll
        for (int pi = 0; pi < 8; pi++) {
            int pix = pix0 + pg * 8 + pi;
            float v = acc[jj][pi];
            if (jg < DIN) {
                int b = pix >> 12, l = pix & 4095;
                g_xm[(size_t)(b * DIN + jg) * LSEQ + l] = v;
            } else {
                g_zs[(size_t)pix * DIN + (jg - DIN)] = silu_f(v);
            }
        }
    }
}

// ================= K2: depthwise conv + silu =================
__global__ void k2_conv(const float* __restrict__ cw, const float* __restrict__ cb)
{
    int idx = blockIdx.x * 256 + threadIdx.x;
    int w_ = idx & 63, h_ = (idx >> 6) & 63;
    int t  = idx >> 12;
    int d  = t % DIN, b = t / DIN;
    const float* src = g_xm + (size_t)(b * DIN + d) * LSEQ;
    float acc = cb[d];
    #pragma unroll
    for (int dy = 0; dy < 3; dy++) {
        int hh = h_ + dy - 1;
        if (hh < 0 || hh > 63) continue;
        #pragma unroll
        for (int dx = 0; dx < 3; dx++) {
            int ww = w_ + dx - 1;
            if (ww < 0 || ww > 63) continue;
            acc = fmaf(src[hh * 64 + ww], cw[d * 9 + dy * 3 + dx], acc);
        }
    }
    float v = silu_f(acc);
    g_x0[idx] = v;
    g_x1[(size_t)(b * DIN + d) * LSEQ + w_ * 64 + h_] = v;
}

// ================= K3: x_proj + dt_proj + softplus =================
__global__ void k3_xproj(const float* __restrict__ xpw, const float* __restrict__ dtw,
                         const float* __restrict__ dtb)
{
    extern __shared__ float sm[];
    float* u_s  = sm;                         // 192*64
    float* wp_s = u_s + 192 * 64;             // 38*192
    float* xd_s = wp_s + 38 * 192;            // 38*65
    float* dw_s = xd_s + 38 * 65;             // 192*6
    const int tid = threadIdx.x;
    const int bk = blockIdx.x >> 6;
    const int b = bk >> 2, k = bk & 3;
    const int l0 = (blockIdx.x & 63) << 6;
    const float* seq = (k & 1) ? g_x1 : g_x0;

    for (int i = tid; i < 192 * 64; i += 256) {
        int d = i >> 6, c = i & 63;
        u_s[i] = seq[(size_t)(b * DIN + d) * LSEQ + l0 + c];
    }
    for (int i = tid; i < 38 * 192; i += 256) wp_s[i] = xpw[k * 38 * 192 + i];
    for (int i = tid; i < 192 * 6;  i += 256) dw_s[i] = dtw[k * 192 * 6 + i];
    __syncthreads();

    const int col = tid & 63, grp = tid >> 6;
    float acc[10];
    #pragma unroll
    for (int j = 0; j < 10; j++) acc[j] = 0.f;
    for (int kk = 0; kk < 192; kk++) {
        float uv = u_s[kk * 64 + col];
        #pragma unroll
        for (int j = 0; j < 10; j++) {
            int row = grp + 4 * j;
            if (row < 38) acc[j] = fmaf(wp_s[row * 192 + kk], uv, acc[j]);
        }
    }
    #pragma unroll
    for (int j = 0; j < 10; j++) {
        int row = grp + 4 * j;
        if (row < 38) xd_s[row * 65 + col] = acc[j];
    }
    __syncthreads();

    const size_t bcbase = (size_t)(b * 4 + k) * LSEQ + l0;
    for (int i = tid; i < 32 * 64; i += 256) {
        int n = i & 31, cc = i >> 5;
        g_bc[(bcbase + cc) * 32 + n] = xd_s[(6 + n) * 65 + cc];
    }
    const int dg = tid >> 6;
    const size_t dbase = (size_t)(b * 4 + k) * DIN * LSEQ;
    for (int j = 0; j < 48; j++) {
        int d = dg + 4 * j;
        float val = dtb[k * DIN + d];
        #pragma unroll
        for (int r = 0; r < 6; r++)
            val = fmaf(dw_s[d * 6 + r], xd_s[r * 65 + col], val);
        val = fmaxf(val, 0.f) + log1pf(__expf(-fabsf(val)));
        g_delta[dbase + (size_t)d * LSEQ + l0 + col] = val;
    }
}

// ================= K4a: local chunk scan (templated direction) =================
// launch covers k in {K0, K0+1}; warp = (pair, chunk), pair = 2 adjacent d's
template<int K0, bool REV>
__global__ void k4a_local(const float* __restrict__ alog)
{
    const int lane = threadIdx.x & 31;
    const int w = blockIdx.x * 8 + (threadIdx.x >> 5);   // 0..6143
    const int chunk = w & (NCHUNK - 1);
    const int pair  = w >> 4;                            // 0..383
    const int half = lane >> 4, n = lane & 15;
    const int kk = pair / 192;                           // 0 or 1
    const int rem = pair - kk * 192;
    const int b = rem / 96;
    const int d = (rem - b * 96) * 2 + half;
    const int k = K0 + kk;
    const int bk = b * 4 + k;
    const int ch = bk * DIN + d;
    const float An2 = -__expf(alog[(k * DIN + d) * NST + n]) * 1.44269504f;

    const float* dptr = g_delta + ((size_t)bk * DIN + d) * LSEQ;
    const float* uptr = (kk ? g_x1 : g_x0) + ((size_t)b * DIN + d) * LSEQ;
    const float* bptr = g_bc + (size_t)bk * LSEQ * 32 + n;   // B broadcast

    float h = 0.f, P = 1.f;
    if (!REV) {
        const int i0 = chunk * CLEN;
        const float4* dp4 = (const float4*)(dptr + i0);
        const float4* up4 = (const float4*)(uptr + i0);
        const float* bp = bptr + (size_t)i0 * 32;
        for (int s = 0; s < CLEN / 4; s++) {
            float4 d4 = dp4[s]; float4 u4 = up4[s];
            float dd[4] = {d4.x, d4.y, d4.z, d4.w};
            float uu[4] = {u4.x, u4.y, u4.z, u4.w};
            #pragma unroll
            for (int j = 0; j < 4; j++) {
                float Bv = __ldg(bp + (s * 4 + j) * 32);
                float a = exp2f(dd[j] * An2);
                h = fmaf(a, h, dd[j] * uu[j] * Bv);
                P *= a;
            }
        }
    } else {
        const int ltop = LSEQ - chunk * CLEN;            // exclusive upper bound
        const float4* dp4 = (const float4*)(dptr + ltop) - 1;
        const float4* up4 = (const float4*)(uptr + ltop) - 1;
        const float* bp = bptr + (size_t)(ltop - 1) * 32;
        for (int s = 0; s < CLEN / 4; s++) {
            float4 d4 = dp4[-s]; float4 u4 = up4[-s];
            float dd[4] = {d4.x, d4.y, d4.z, d4.w};
            float uu[4] = {u4.x, u4.y, u4.z, u4.w};
            #pragma unroll
            for (int j = 0; j < 4; j++) {
                const int e = 3 - j;                     // element within float4
                float Bv = __ldg(bp - (s * 4 + j) * 32);
                float a = exp2f(dd[e] * An2);
                h = fmaf(a, h, dd[e] * uu[e] * Bv);
                P *= a;
            }
        }
    }
    g_P [(ch * NCHUNK + chunk) * NST + n] = P;
    g_he[(ch * NCHUNK + chunk) * NST + n] = h;
}

// ================= K4b: carry across chunks =================
__global__ void k4b_carry()
{
    int idx = blockIdx.x * 256 + threadIdx.x;   // 0..24575
    int ch = idx >> 4, n = idx & 15;
    float H = 0.f;
    #pragma unroll
    for (int c = 0; c < NCHUNK; c++) {
        int o = (ch * NCHUNK + c) * NST + n;
        g_H[o] = H;
        H = fmaf(g_P[o], H, g_he[o]);
    }
}

// ================= K4c: seeded chunk scan, emit y =================
template<int K0, bool REV>
__global__ void k4c_emit(const float* __restrict__ alog, const float* __restrict__ ds)
{
    const int lane = threadIdx.x & 31;
    const int w = blockIdx.x * 8 + (threadIdx.x >> 5);
    const int chunk = w & (NCHUNK - 1);
    const int pair  = w >> 4;
    const int half = lane >> 4, n = lane & 15;
    const int kk = pair / 192;
    const int rem = pair - kk * 192;
    const int b = rem / 96;
    const int d = (rem - b * 96) * 2 + half;
    const int k = K0 + kk;
    const int bk = b * 4 + k;
    const int ch = bk * DIN + d;
    const float An2 = -__expf(alog[(k * DIN + d) * NST + n]) * 1.44269504f;
    const float Dd = ds[k * DIN + d];
    const bool tr = kk;                                   // k&1

    const float* dptr = g_delta + ((size_t)bk * DIN + d) * LSEQ;
    const float* uptr = (kk ? g_x1 : g_x0) + ((size_t)b * DIN + d) * LSEQ;
    const float* bcp  = g_bc + (size_t)bk * LSEQ * 32 + lane;
    float* yp = g_y + ((size_t)(k * BATCH + b) * DIN + d) * LSEQ;

    float h = g_H[(ch * NCHUNK + chunk) * NST + n];

    if (!REV) {
        const int i0 = chunk * CLEN;
        const float4* dp4 = (const float4*)(dptr + i0);
        const float4* up4 = (const float4*)(uptr + i0);
        const float* bp = bcp + (size_t)i0 * 32;
        for (int s = 0; s < CLEN / 4; s++) {
            float4 d4 = dp4[s]; float4 u4 = up4[s];
            float dd[4] = {d4.x, d4.y, d4.z, d4.w};
            float uu[4] = {u4.x, u4.y, u4.z, u4.w};
            #pragma unroll
            for (int j = 0; j < 4; j++) {
                float v = __ldg(bp + (s * 4 + j) * 32);
                float o = __shfl_xor_sync(0xffffffffu, v, 16);
                float Bv = half ? o : v;
                float Cv = half ? v : o;
                float a = exp2f(dd[j] * An2);
                h = fmaf(a, h, dd[j] * uu[j] * Bv);
                float t = h * Cv;
                t += __shfl_xor_sync(0xffffffffu, t, 8);
                t += __shfl_xor_sync(0xffffffffu, t, 4);
                t += __shfl_xor_sync(0xffffffffu, t, 2);
                t += __shfl_xor_sync(0xffffffffu, t, 1);
                if (n == 0) {
                    int l = i0 + s * 4 + j;
                    int lr = tr ? (((l & 63) << 6) | (l >> 6)) : l;
                    yp[lr] = fmaf(Dd, uu[j], t);
                }
            }
        }
    } else {
        const int ltop = LSEQ - chunk * CLEN;
        const float4* dp4 = (const float4*)(dptr + ltop) - 1;
        const float4* up4 = (const float4*)(uptr + ltop) - 1;
        const float* bp = bcp + (size_t)(ltop - 1) * 32;
        for (int s = 0; s < CLEN / 4; s++) {
            float4 d4 = dp4[-s]; float4 u4 = up4[-s];
            float dd[4] = {d4.x, d4.y, d4.z, d4.w};
            float uu[4] = {u4.x, u4.y, u4.z, u4.w};
            #pragma unroll
            for (int j = 0; j < 4; j++) {
                const int e = 3 - j;
                float v = __ldg(bp - (s * 4 + j) * 32);
                float o = __shfl_xor_sync(0xffffffffu, v, 16);
                float Bv = half ? o : v;
                float Cv = half ? v : o;
                float a = exp2f(dd[e] * An2);
                h = fmaf(a, h, dd[e] * uu[e] * Bv);
                float t = h * Cv;
                t += __shfl_xor_sync(0xffffffffu, t, 8);
                t += __shfl_xor_sync(0xffffffffu, t, 4);
                t += __shfl_xor_sync(0xffffffffu, t, 2);
                t += __shfl_xor_sync(0xffffffffu, t, 1);
                if (n == 0) {
                    int l = ltop - 1 - (s * 4 + j);
                    int lr = tr ? (((l & 63) << 6) | (l >> 6)) : l;
                    yp[lr] = fmaf(Dd, uu[e], t);
                }
            }
        }
    }
}

// ================= K5: merge + out-LN + gate + out_proj + residual =================
__global__ void k5_final(const float* __restrict__ onw, const float* __restrict__ onb,
                         const float* __restrict__ wout, float* __restrict__ out)
{
    extern __shared__ float sm[];
    float* yc = sm;                  // 192*36
    float* ws = sm + 192 * 36;       // 96*192
    const int tid = threadIdx.x, lane = tid & 31, warp = tid >> 5;
    const int b = blockIdx.x >> 7;
    const int l0 = (blockIdx.x & 127) << 5;

    for (int i = tid; i < 192 * 32; i += 256) {
        int d = i >> 5, p = i & 31;
        size_t off = (size_t)d * LSEQ + l0 + p;
        float v = g_y[((size_t)(0 * BATCH + b) * DIN) * LSEQ + off]
                + g_y[((size_t)(1 * BATCH + b) * DIN) * LSEQ + off]
                + g_y[((size_t)(2 * BATCH + b) * DIN) * LSEQ + off]
                + g_y[((size_t)(3 * BATCH + b) * DIN) * LSEQ + off];
        yc[d * 36 + p] = v;
    }
    for (int i = tid; i < 96 * 192; i += 256) ws[i] = wout[i];
    __syncthreads();

    #pragma unroll
    for (int pp = 0; pp < 4; pp++) {
        const int p = warp * 4 + pp;
        float s = 0.f, s2 = 0.f, vv[6];
        #pragma unroll
        for (int j = 0; j < 6; j++) {
            float v = yc[(lane + 32 * j) * 36 + p];
            vv[j] = v; s += v; s2 += v * v;
        }
        #pragma unroll
        for (int o = 16; o > 0; o >>= 1) {
            s  += __shfl_xor_sync(0xffffffffu, s,  o);
            s2 += __shfl_xor_sync(0xffffffffu, s2, o);
        }
        float mu = s * (1.f / 192.f);
        float var = s2 * (1.f / 192.f) - mu * mu;
        float rstd = rsqrtf(var + 1e-5f);
        size_t zbase = ((size_t)(b * LSEQ + l0 + p)) * DIN;
        #pragma unroll
        for (int j = 0; j < 6; j++) {
            int dd = lane + 32 * j;
            float g = (vv[j] - mu) * rstd * onw[dd] + onb[dd];
            yc[dd * 36 + p] = g * g_zs[zbase + dd];
        }
    }
    __syncthreads();

    const int og = tid >> 3;
    const int pg = tid & 7;
    float acc[3][4];
    #pragma unroll
    for (int a = 0; a < 3; a++)
        #pragma unroll
        for (int c = 0; c < 4; c++) acc[a][c] = 0.f;

    #pragma unroll 4
    for (int dd = 0; dd < 192; dd++) {
        float4 gv = *(const float4*)&yc[dd * 36 + pg * 4];
        float g4[4] = {gv.x, gv.y, gv.z, gv.w};
        #pragma unroll
        for (int oi = 0; oi < 3; oi++) {
            float w2 = ws[(og * 3 + oi) * 192 + dd];
            #pragma unroll
            for (int pi = 0; pi < 4; pi++)
                acc[oi][pi] = fmaf(w2, g4[pi], acc[oi][pi]);
        }
    }
    #pragma unroll
    for (int oi = 0; oi < 3; oi++)
        #pragma unroll
        for (int pi = 0; pi < 4; pi++) {
            int o = og * 3 + oi;
            size_t pix = (size_t)b * LSEQ + l0 + pg * 4 + pi;
            out[pix * 96 + o] = g_diff[pix * 96 + o] + acc[oi][pi];
        }
}

// ================= launch =================
extern "C" void kernel_launch(void* const* d_in, const int* in_sizes, int n_in,
                              void* d_out, int out_size)
{
    const float* x     = (const float*)d_in[0];
    const float* y     = (const float*)d_in[1];
    const float* ln_w  = (const float*)d_in[2];
    const float* ln_b  = (const float*)d_in[3];
    const float* ipw   = (const float*)d_in[4];
    const float* cw    = (const float*)d_in[5];
    const float* cb    = (const float*)d_in[6];
    const float* xpw   = (const float*)d_in[7];
    const float* dtw   = (const float*)d_in[8];
    const float* dtb   = (const float*)d_in[9];
    const float* alog  = (const float*)d_in[10];
    const float* ds    = (const float*)d_in[11];
    const float* onw   = (const float*)d_in[12];
    const float* onb   = (const float*)d_in[13];
    const float* wout  = (const float*)d_in[14];
    float* out = (float*)d_out;

    const int smem1 = (96 * 64 + 96 * 128) * 4;
    const int smem3 = (192 * 64 + 38 * 192 + 38 * 65 + 192 * 6) * 4;
    const int smem5 = (192 * 36 + 96 * 192) * 4;
    cudaFuncSetAttribute(k1_prologue, cudaFuncAttributeMaxDynamicSharedMemorySize, smem1);
    cudaFuncSetAttribute(k3_xproj,   cudaFuncAttributeMaxDynamicSharedMemorySize, smem3);
    cudaFuncSetAttribute(k5_final,   cudaFuncAttributeMaxDynamicSharedMemorySize, smem5);

    // 384 pairs * 16 chunks = 6144 warps = 768 blocks per direction-group
    k1_prologue<<<dim3(128, 3), 256, smem1>>>(x, y, ln_w, ln_b, ipw);
    k2_conv<<<(BATCH * DIN * LSEQ) / 256, 256>>>(cw, cb);
    k3_xproj<<<BATCH * 4 * (LSEQ / 64), 256, smem3>>>(xpw, dtw, dtb);
    k4a_local<0, false><<<768, 256>>>(alog);
    k4a_local<2, true ><<<768, 256>>>(alog);
    k4b_carry<<<NCH * NST / 256, 256>>>();
    k4c_emit<0, false><<<768, 256>>>(alog, ds);
    k4c_emit<2, true ><<<768, 256>>>(alog, ds);
    k5_final<<<BATCH * (LSEQ / 32), 256, smem5>>>(onw, onb, wout, out);
}

// round 5
// speedup vs baseline: 2.8970x; 1.2078x over previous
#include <cuda_runtime.h>
#include <math.h>

#define BATCH 2
#define CDIM  96
#define DIN   192
#define NST   16
#define LSEQ  4096
#define NPIX  (BATCH*LSEQ)
#define NCH   (BATCH*4*DIN)     // 1536 scan channels
#define NCHUNK 16
#define CLEN  (LSEQ/NCHUNK)     // 256

// ---------------- persistent device scratch ----------------
__device__ float  g_diff [NPIX*CDIM];
__device__ float  g_zs   [NPIX*DIN];
__device__ float  g_xm   [BATCH*DIN*LSEQ];
__device__ float  g_x0   [BATCH*DIN*LSEQ];
__device__ float  g_x1   [BATCH*DIN*LSEQ];
__device__ float  g_delta[BATCH*4*DIN*LSEQ];
__device__ float  g_bb   [BATCH*4*LSEQ*16];   // B only, for k4a
__device__ float4 g_bc4  [BATCH*4*LSEQ*8];    // (B_n, C_n, B_{n+8}, C_{n+8})
__device__ float  g_y    [4*BATCH*DIN*LSEQ];
__device__ float  g_P    [NCH*NCHUNK*NST];
__device__ float  g_he   [NCH*NCHUNK*NST];
__device__ float  g_H    [NCH*NCHUNK*NST];

__device__ __forceinline__ float silu_f(float v){ return v / (1.f + __expf(-v)); }

// ================= K1: diff + LN + in_proj GEMM =================
__global__ void k1_prologue(const float* __restrict__ x, const float* __restrict__ y,
                            const float* __restrict__ lnw, const float* __restrict__ lnb,
                            const float* __restrict__ wproj)
{
    extern __shared__ float sm[];
    float* A_s = sm;            // 96*64
    float* W_s = sm + 96*64;    // 96*128
    const int tid = threadIdx.x, lane = tid & 31, warp = tid >> 5;
    const int pix0 = blockIdx.x * 64;
    const int oc = blockIdx.y;

    for (int pp = 0; pp < 8; pp++) {
        const int p = warp * 8 + pp;
        const int base = (pix0 + p) * CDIM;
        float vv[3]; float s = 0.f, s2 = 0.f;
        #pragma unroll
        for (int j = 0; j < 3; j++) {
            int ch = lane + 32 * j;
            float d = fabsf(x[base + ch] - y[base + ch]);
            if (oc == 0) g_diff[base + ch] = d;
            vv[j] = d; s += d; s2 += d * d;
        }
        #pragma unroll
        for (int o = 16; o > 0; o >>= 1) {
            s  += __shfl_xor_sync(0xffffffffu, s,  o);
            s2 += __shfl_xor_sync(0xffffffffu, s2, o);
        }
        float mu = s * (1.f / 96.f);
        float var = s2 * (1.f / 96.f) - mu * mu;
        float rstd = rsqrtf(var + 1e-5f);
        #pragma unroll
        for (int j = 0; j < 3; j++) {
            int ch = lane + 32 * j;
            A_s[ch * 64 + p] = (vv[j] - mu) * rstd * lnw[ch] + lnb[ch];
        }
    }
    for (int i = tid; i < 96 * 128; i += 256) {
        int kk = i % 96, j = i / 96;
        W_s[kk * 128 + j] = wproj[(oc * 128 + j) * 96 + kk];
    }
    __syncthreads();

    const int pg = tid & 7;
    const int og = tid >> 3;
    const float4* A4 = (const float4*)A_s;
    const float4* W4 = (const float4*)W_s;

    float acc[4][8];
    #pragma unroll
    for (int a = 0; a < 4; a++)
        #pragma unroll
        for (int b = 0; b < 8; b++) acc[a][b] = 0.f;

    #pragma unroll 4
    for (int kk = 0; kk < 96; kk++) {
        float4 a0 = A4[kk * 16 + pg * 2];
        float4 a1 = A4[kk * 16 + pg * 2 + 1];
        float4 w  = W4[kk * 32 + og];
        float ws4[4] = {w.x, w.y, w.z, w.w};
        float as8[8] = {a0.x, a0.y, a0.z, a0.w, a1.x, a1.y, a1.z, a1.w};
        #pragma unroll
        for (int jj = 0; jj < 4; jj++)
            #pragma unroll
            for (int pi = 0; pi < 8; pi++)
                acc[jj][pi] = fmaf(ws4[jj], as8[pi], acc[jj][pi]);
    }

    #pragma unroll
    for (int jj = 0; jj < 4; jj++) {
        int jg = oc * 128 + og * 4 + jj;
        #pragma unroll
        for (int pi = 0; pi < 8; pi++) {
            int pix = pix0 + pg * 8 + pi;
            float v = acc[jj][pi];
            if (jg < DIN) {
                int b = pix >> 12, l = pix & 4095;
                g_xm[(size_t)(b * DIN + jg) * LSEQ + l] = v;
            } else {
                g_zs[(size_t)pix * DIN + (jg - DIN)] = silu_f(v);
            }
        }
    }
}

// ================= K2: depthwise conv + silu =================
__global__ void k2_conv(const float* __restrict__ cw, const float* __restrict__ cb)
{
    int idx = blockIdx.x * 256 + threadIdx.x;
    int w_ = idx & 63, h_ = (idx >> 6) & 63;
    int t  = idx >> 12;
    int d  = t % DIN, b = t / DIN;
    const float* src = g_xm + (size_t)(b * DIN + d) * LSEQ;
    float acc = cb[d];
    #pragma unroll
    for (int dy = 0; dy < 3; dy++) {
        int hh = h_ + dy - 1;
        if (hh < 0 || hh > 63) continue;
        #pragma unroll
        for (int dx = 0; dx < 3; dx++) {
            int ww = w_ + dx - 1;
            if (ww < 0 || ww > 63) continue;
            acc = fmaf(src[hh * 64 + ww], cw[d * 9 + dy * 3 + dx], acc);
        }
    }
    float v = silu_f(acc);
    g_x0[idx] = v;
    g_x1[(size_t)(b * DIN + d) * LSEQ + w_ * 64 + h_] = v;
}

// ================= K3: x_proj + dt_proj + softplus =================
__global__ void k3_xproj(const float* __restrict__ xpw, const float* __restrict__ dtw,
                         const float* __restrict__ dtb)
{
    extern __shared__ float sm[];
    float* u_s  = sm;                         // 192*64
    float* wp_s = u_s + 192 * 64;             // 38*192
    float* xd_s = wp_s + 38 * 192;            // 38*65
    float* dw_s = xd_s + 38 * 65;             // 192*6
    const int tid = threadIdx.x;
    const int bk = blockIdx.x >> 6;
    const int b = bk >> 2, k = bk & 3;
    const int l0 = (blockIdx.x & 63) << 6;
    const float* seq = (k & 1) ? g_x1 : g_x0;

    for (int i = tid; i < 192 * 64; i += 256) {
        int d = i >> 6, c = i & 63;
        u_s[i] = seq[(size_t)(b * DIN + d) * LSEQ + l0 + c];
    }
    for (int i = tid; i < 38 * 192; i += 256) wp_s[i] = xpw[k * 38 * 192 + i];
    for (int i = tid; i < 192 * 6;  i += 256) dw_s[i] = dtw[k * 192 * 6 + i];
    __syncthreads();

    const int col = tid & 63, grp = tid >> 6;
    float acc[10];
    #pragma unroll
    for (int j = 0; j < 10; j++) acc[j] = 0.f;
    for (int kk = 0; kk < 192; kk++) {
        float uv = u_s[kk * 64 + col];
        #pragma unroll
        for (int j = 0; j < 10; j++) {
            int row = grp + 4 * j;
            if (row < 38) acc[j] = fmaf(wp_s[row * 192 + kk], uv, acc[j]);
        }
    }
    #pragma unroll
    for (int j = 0; j < 10; j++) {
        int row = grp + 4 * j;
        if (row < 38) xd_s[row * 65 + col] = acc[j];
    }
    __syncthreads();

    const size_t bcbase = (size_t)(b * 4 + k) * LSEQ + l0;
    // B-only layout for k4a (rows 6..21)
    for (int i = tid; i < 16 * 64; i += 256) {
        int n = i & 15, cc = i >> 4;
        g_bb[(bcbase + cc) * 16 + n] = xd_s[(6 + n) * 65 + cc];
    }
    // interleaved (B,C) float4 layout for k4c
    for (int i = tid; i < 8 * 64; i += 256) {
        int n8 = i & 7, cc = i >> 3;
        float4 v;
        v.x = xd_s[(6  + n8) * 65 + cc];   // B_{n8}
        v.y = xd_s[(22 + n8) * 65 + cc];   // C_{n8}
        v.z = xd_s[(14 + n8) * 65 + cc];   // B_{n8+8}
        v.w = xd_s[(30 + n8) * 65 + cc];   // C_{n8+8}
        g_bc4[(bcbase + cc) * 8 + n8] = v;
    }
    const int dg = tid >> 6;
    const size_t dbase = (size_t)(b * 4 + k) * DIN * LSEQ;
    for (int j = 0; j < 48; j++) {
        int d = dg + 4 * j;
        float val = dtb[k * DIN + d];
        #pragma unroll
        for (int r = 0; r < 6; r++)
            val = fmaf(dw_s[d * 6 + r], xd_s[r * 65 + col], val);
        val = fmaxf(val, 0.f) + log1pf(__expf(-fabsf(val)));
        g_delta[dbase + (size_t)d * LSEQ + l0 + col] = val;
    }
}

// ================= K4a: local chunk scan (2 channels/warp, 16 states/lane-group) ==
// warps per group: 384 pairs * 16 chunks = 6144; grid dim3(768, 2)
template<bool REV>
__device__ __forceinline__ void k4a_body(const int K0, const float* __restrict__ alog)
{
    const int lane = threadIdx.x & 31;
    const int w = blockIdx.x * 8 + (threadIdx.x >> 5);   // 0..6143
    const int chunk = w & (NCHUNK - 1);
    const int pair  = w >> 4;                            // 0..383
    const int half = lane >> 4, n = lane & 15;
    const int kk = pair / 192;                           // 0 or 1
    const int rem = pair - kk * 192;                     // 0..191
    const int b = rem / 96;                              // 0..1
    const int d = (rem - b * 96) * 2 + half;             // 0..191
    const int k = K0 + kk;
    const int bk = b * 4 + k;
    const int ch = bk * DIN + d;
    const float An2 = -__expf(alog[(k * DIN + d) * NST + n]) * 1.44269504f;

    const float* dptr = g_delta + ((size_t)bk * DIN + d) * LSEQ;
    const float* uptr = (kk ? g_x1 : g_x0) + ((size_t)b * DIN + d) * LSEQ;
    const float* bptr = g_bb + (size_t)bk * LSEQ * 16 + n;

    float h = 0.f, sdel = 0.f;
    if (!REV) {
        const int i0 = chunk * CLEN;
        const float4* dp4 = (const float4*)(dptr + i0);
        const float4* up4 = (const float4*)(uptr + i0);
        const float* bp = bptr + (size_t)i0 * 16;
        #pragma unroll 2
        for (int s = 0; s < CLEN / 4; s++) {
            float4 d4 = dp4[s]; float4 u4 = up4[s];
            float dd[4] = {d4.x, d4.y, d4.z, d4.w};
            float uu[4] = {u4.x, u4.y, u4.z, u4.w};
            #pragma unroll
            for (int j = 0; j < 4; j++) {
                float Bv = __ldg(bp + (s * 4 + j) * 16);
                float a = exp2f(dd[j] * An2);
                h = fmaf(a, h, dd[j] * uu[j] * Bv);
                sdel += dd[j];
            }
        }
    } else {
        const int ltop = LSEQ - chunk * CLEN;
        const float4* dp4 = (const float4*)(dptr + ltop) - 1;
        const float4* up4 = (const float4*)(uptr + ltop) - 1;
        const float* bp = bptr + (size_t)(ltop - 1) * 16;
        #pragma unroll 2
        for (int s = 0; s < CLEN / 4; s++) {
            float4 d4 = dp4[-s]; float4 u4 = up4[-s];
            float dd[4] = {d4.x, d4.y, d4.z, d4.w};
            float uu[4] = {u4.x, u4.y, u4.z, u4.w};
            #pragma unroll
            for (int j = 0; j < 4; j++) {
                const int e = 3 - j;
                float Bv = __ldg(bp - (s * 4 + j) * 16);
                float a = exp2f(dd[e] * An2);
                h = fmaf(a, h, dd[e] * uu[e] * Bv);
                sdel += dd[e];
            }
        }
    }
    g_P [(ch * NCHUNK + chunk) * NST + n] = exp2f(An2 * sdel);
    g_he[(ch * NCHUNK + chunk) * NST + n] = h;
}

__global__ void k4a_scan(const float* __restrict__ alog)
{
    if (blockIdx.y == 0) k4a_body<false>(0, alog);
    else                 k4a_body<true >(2, alog);
}

// ================= K4b: carry across chunks =================
__global__ void k4b_carry()
{
    int idx = blockIdx.x * 256 + threadIdx.x;   // 0..24575
    int ch = idx >> 4, n = idx & 15;
    float H = 0.f;
    #pragma unroll
    for (int c = 0; c < NCHUNK; c++) {
        int o = (ch * NCHUNK + c) * NST + n;
        g_H[o] = H;
        H = fmaf(g_P[o], H, g_he[o]);
    }
}

// ================= K4c: seeded scan, emit y (4 channels/warp, 2 states/lane) =====
// warps per group: 192 quads * 16 chunks = 3072; grid dim3(384, 2)
template<bool REV>
__device__ __forceinline__ void k4c_body(const int K0, const float* __restrict__ alog,
                                         const float* __restrict__ ds)
{
    const int lane = threadIdx.x & 31;
    const int w = blockIdx.x * 8 + (threadIdx.x >> 5);   // 0..3071
    const int chunk = w & (NCHUNK - 1);                  // 0..15
    const int quad  = w >> 4;                            // 0..191
    const int c2 = lane >> 3;                            // 0..3: channel in warp
    const int n0 = lane & 7;                             // states n0, n0+8
    const int kk = quad / 96;                            // 0 or 1
    const int rem = quad - kk * 96;                      // 0..95
    const int b = rem / 48;                              // 0..1
    const int d = (rem - b * 48) * 4 + c2;               // 0..191
    const int k = K0 + kk;
    const int bk = b * 4 + k;
    const int ch = bk * DIN + d;

    const float An0 = -__expf(alog[(k * DIN + d) * NST + n0]) * 1.44269504f;
    const float An1 = -__expf(alog[(k * DIN + d) * NST + n0 + 8]) * 1.44269504f;
    const float Dd = ds[k * DIN + d];

    const float* dptr = g_delta + ((size_t)bk * DIN + d) * LSEQ;
    const float* uptr = (kk ? g_x1 : g_x0) + ((size_t)b * DIN + d) * LSEQ;
    const float4* bcp = g_bc4 + (size_t)bk * LSEQ * 8 + n0;
    float* yp = g_y + ((size_t)(k * BATCH + b) * DIN + d) * LSEQ;

    float h0 = g_H[(ch * NCHUNK + chunk) * NST + n0];
    float h1 = g_H[(ch * NCHUNK + chunk) * NST + n0 + 8];

    if (!REV) {
        const int i0 = chunk * CLEN;
        const float4* dp4 = (const float4*)(dptr + i0);
        const float4* up4 = (const float4*)(uptr + i0);
        const float4* bp = bcp + (size_t)i0 * 8;
        #pragma unroll 2
        for (int s = 0; s < CLEN / 4; s++) {
            float4 dv = dp4[s]; float4 uv = up4[s];
            float dd[4] = {dv.x, dv.y, dv.z, dv.w};
            float uu[4] = {uv.x, uv.y, uv.z, uv.w};
            #pragma unroll
            for (int j = 0; j < 4; j++) {
                float4 bc = __ldg(bp + (s * 4 + j) * 8);
                float du = dd[j] * uu[j];
                float a0 = exp2f(dd[j] * An0);
                float a1 = exp2f(dd[j] * An1);
                h0 = fmaf(a0, h0, du * bc.x);
                h1 = fmaf(a1, h1, du * bc.z);
                float t = fmaf(h1, bc.w, h0 * bc.y);
                t += __shfl_xor_sync(0xffffffffu, t, 4);
                t += __shfl_xor_sync(0xffffffffu, t, 2);
                t += __shfl_xor_sync(0xffffffffu, t, 1);
                if (n0 == 0) {
                    int l = i0 + s * 4 + j;
                    int lr = kk ? (((l & 63) << 6) | (l >> 6)) : l;
                    yp[lr] = fmaf(Dd, uu[j], t);
                }
            }
        }
    } else {
        const int ltop = LSEQ - chunk * CLEN;
        const float4* dp4 = (const float4*)(dptr + ltop) - 1;
        const float4* up4 = (const float4*)(uptr + ltop) - 1;
        const float4* bp = bcp + (size_t)(ltop - 1) * 8;
        #pragma unroll 2
        for (int s = 0; s < CLEN / 4; s++) {
            float4 dv = dp4[-s]; float4 uv = up4[-s];
            float dd[4] = {dv.x, dv.y, dv.z, dv.w};
            float uu[4] = {uv.x, uv.y, uv.z, uv.w};
            #pragma unroll
            for (int j = 0; j < 4; j++) {
                const int e = 3 - j;
                float4 bc = __ldg(bp - (s * 4 + j) * 8);
                float du = dd[e] * uu[e];
                float a0 = exp2f(dd[e] * An0);
                float a1 = exp2f(dd[e] * An1);
                h0 = fmaf(a0, h0, du * bc.x);
                h1 = fmaf(a1, h1, du * bc.z);
                float t = fmaf(h1, bc.w, h0 * bc.y);
                t += __shfl_xor_sync(0xffffffffu, t, 4);
                t += __shfl_xor_sync(0xffffffffu, t, 2);
                t += __shfl_xor_sync(0xffffffffu, t, 1);
                if (n0 == 0) {
                    int l = ltop - 1 - (s * 4 + j);
                    int lr = kk ? (((l & 63) << 6) | (l >> 6)) : l;
                    yp[lr] = fmaf(Dd, uu[e], t);
                }
            }
        }
    }
}

__global__ void k4c_scan(const float* __restrict__ alog, const float* __restrict__ ds)
{
    if (blockIdx.y == 0) k4c_body<false>(0, alog, ds);
    else                 k4c_body<true >(2, alog, ds);
}

// ================= K5: merge + out-LN + gate + out_proj + residual =================
__global__ void k5_final(const float* __restrict__ onw, const float* __restrict__ onb,
                         const float* __restrict__ wout, float* __restrict__ out)
{
    extern __shared__ float sm[];
    float* yc = sm;                  // 192*36
    float* ws = sm + 192 * 36;       // 96*192
    const int tid = threadIdx.x, lane = tid & 31, warp = tid >> 5;
    const int b = blockIdx.x >> 7;
    const int l0 = (blockIdx.x & 127) << 5;

    for (int i = tid; i < 192 * 32; i += 256) {
        int d = i >> 5, p = i & 31;
        size_t off = (size_t)d * LSEQ + l0 + p;
        float v = g_y[((size_t)(0 * BATCH + b) * DIN) * LSEQ + off]
                + g_y[((size_t)(1 * BATCH + b) * DIN) * LSEQ + off]
                + g_y[((size_t)(2 * BATCH + b) * DIN) * LSEQ + off]
                + g_y[((size_t)(3 * BATCH + b) * DIN) * LSEQ + off];
        yc[d * 36 + p] = v;
    }
    for (int i = tid; i < 96 * 192; i += 256) ws[i] = wout[i];
    __syncthreads();

    #pragma unroll
    for (int pp = 0; pp < 4; pp++) {
        const int p = warp * 4 + pp;
        float s = 0.f, s2 = 0.f, vv[6];
        #pragma unroll
        for (int j = 0; j < 6; j++) {
            float v = yc[(lane + 32 * j) * 36 + p];
            vv[j] = v; s += v; s2 += v * v;
        }
        #pragma unroll
        for (int o = 16; o > 0; o >>= 1) {
            s  += __shfl_xor_sync(0xffffffffu, s,  o);
            s2 += __shfl_xor_sync(0xffffffffu, s2, o);
        }
        float mu = s * (1.f / 192.f);
        float var = s2 * (1.f / 192.f) - mu * mu;
        float rstd = rsqrtf(var + 1e-5f);
        size_t zbase = ((size_t)(b * LSEQ + l0 + p)) * DIN;
        #pragma unroll
        for (int j = 0; j < 6; j++) {
            int dd = lane + 32 * j;
            float g = (vv[j] - mu) * rstd * onw[dd] + onb[dd];
            yc[dd * 36 + p] = g * g_zs[zbase + dd];
        }
    }
    __syncthreads();

    const int og = tid >> 3;
    const int pg = tid & 7;
    float acc[3][4];
    #pragma unroll
    for (int a = 0; a < 3; a++)
        #pragma unroll
        for (int c = 0; c < 4; c++) acc[a][c] = 0.f;

    #pragma unroll 4
    for (int dd = 0; dd < 192; dd++) {
        float4 gv = *(const float4*)&yc[dd * 36 + pg * 4];
        float g4[4] = {gv.x, gv.y, gv.z, gv.w};
        #pragma unroll
        for (int oi = 0; oi < 3; oi++) {
            float w2 = ws[(og * 3 + oi) * 192 + dd];
            #pragma unroll
            for (int pi = 0; pi < 4; pi++)
                acc[oi][pi] = fmaf(w2, g4[pi], acc[oi][pi]);
        }
    }
    #pragma unroll
    for (int oi = 0; oi < 3; oi++)
        #pragma unroll
        for (int pi = 0; pi < 4; pi++) {
            int o = og * 3 + oi;
            size_t pix = (size_t)b * LSEQ + l0 + pg * 4 + pi;
            out[pix * 96 + o] = g_diff[pix * 96 + o] + acc[oi][pi];
        }
}

// ================= launch =================
extern "C" void kernel_launch(void* const* d_in, const int* in_sizes, int n_in,
                              void* d_out, int out_size)
{
    const float* x     = (const float*)d_in[0];
    const float* y     = (const float*)d_in[1];
    const float* ln_w  = (const float*)d_in[2];
    const float* ln_b  = (const float*)d_in[3];
    const float* ipw   = (const float*)d_in[4];
    const float* cw    = (const float*)d_in[5];
    const float* cb    = (const float*)d_in[6];
    const float* xpw   = (const float*)d_in[7];
    const float* dtw   = (const float*)d_in[8];
    const float* dtb   = (const float*)d_in[9];
    const float* alog  = (const float*)d_in[10];
    const float* ds    = (const float*)d_in[11];
    const float* onw   = (const float*)d_in[12];
    const float* onb   = (const float*)d_in[13];
    const float* wout  = (const float*)d_in[14];
    float* out = (float*)d_out;

    const int smem1 = (96 * 64 + 96 * 128) * 4;
    const int smem3 = (192 * 64 + 38 * 192 + 38 * 65 + 192 * 6) * 4;
    const int smem5 = (192 * 36 + 96 * 192) * 4;
    cudaFuncSetAttribute(k1_prologue, cudaFuncAttributeMaxDynamicSharedMemorySize, smem1);
    cudaFuncSetAttribute(k3_xproj,   cudaFuncAttributeMaxDynamicSharedMemorySize, smem3);
    cudaFuncSetAttribute(k5_final,   cudaFuncAttributeMaxDynamicSharedMemorySize, smem5);

    k1_prologue<<<dim3(128, 3), 256, smem1>>>(x, y, ln_w, ln_b, ipw);
    k2_conv<<<(BATCH * DIN * LSEQ) / 256, 256>>>(cw, cb);
    k3_xproj<<<BATCH * 4 * (LSEQ / 64), 256, smem3>>>(xpw, dtw, dtb);
    k4a_scan<<<dim3(768, 2), 256>>>(alog);
    k4b_carry<<<NCH * NST / 256, 256>>>();
    k4c_scan<<<dim3(384, 2), 256>>>(alog, ds);
    k5_final<<<BATCH * (LSEQ / 32), 256, smem5>>>(onw, onb, wout, out);
}

// round 6
// speedup vs baseline: 3.1172x; 1.0760x over previous
#include <cuda_runtime.h>
#include <math.h>

#define BATCH 2
#define CDIM  96
#define DIN   192
#define NST   16
#define LSEQ  4096
#define NPIX  (BATCH*LSEQ)
#define NCH   (BATCH*4*DIN)     // 1536 scan channels
#define NCHUNK 16
#define CLEN  (LSEQ/NCHUNK)     // 256

// ---------------- persistent device scratch ----------------
__device__ float  g_diff [NPIX*CDIM];
__device__ float  g_zs   [NPIX*DIN];
__device__ float  g_xm   [BATCH*DIN*LSEQ];
__device__ float  g_x0   [BATCH*DIN*LSEQ];
__device__ float  g_x1   [BATCH*DIN*LSEQ];
__device__ float  g_delta[BATCH*4*DIN*LSEQ];
__device__ float  g_bb   [BATCH*4*LSEQ*16];   // B only, for k4a
__device__ float4 g_bc4  [BATCH*4*LSEQ*8];    // (B_n, C_n, B_{n+8}, C_{n+8})
__device__ float  g_y    [4*BATCH*DIN*LSEQ];  // per-direction y, scan-native order
__device__ float  g_ysum [BATCH*DIN*LSEQ];    // merged y, canonical row-major
__device__ float  g_P    [NCH*NCHUNK*NST];
__device__ float  g_he   [NCH*NCHUNK*NST];
__device__ float  g_H    [NCH*NCHUNK*NST];

__device__ __forceinline__ float silu_f(float v){ return v / (1.f + __expf(-v)); }

// ================= K1: diff + LN + in_proj GEMM =================
__global__ void k1_prologue(const float* __restrict__ x, const float* __restrict__ y,
                            const float* __restrict__ lnw, const float* __restrict__ lnb,
                            const float* __restrict__ wproj)
{
    extern __shared__ float sm[];
    float* A_s = sm;            // 96*64
    float* W_s = sm + 96*64;    // 96*128
    const int tid = threadIdx.x, lane = tid & 31, warp = tid >> 5;
    const int pix0 = blockIdx.x * 64;
    const int oc = blockIdx.y;

    for (int pp = 0; pp < 8; pp++) {
        const int p = warp * 8 + pp;
        const int base = (pix0 + p) * CDIM;
        float vv[3]; float s = 0.f, s2 = 0.f;
        #pragma unroll
        for (int j = 0; j < 3; j++) {
            int ch = lane + 32 * j;
            float d = fabsf(x[base + ch] - y[base + ch]);
            if (oc == 0) g_diff[base + ch] = d;
            vv[j] = d; s += d; s2 += d * d;
        }
        #pragma unroll
        for (int o = 16; o > 0; o >>= 1) {
            s  += __shfl_xor_sync(0xffffffffu, s,  o);
            s2 += __shfl_xor_sync(0xffffffffu, s2, o);
        }
        float mu = s * (1.f / 96.f);
        float var = s2 * (1.f / 96.f) - mu * mu;
        float rstd = rsqrtf(var + 1e-5f);
        #pragma unroll
        for (int j = 0; j < 3; j++) {
            int ch = lane + 32 * j;
            A_s[ch * 64 + p] = (vv[j] - mu) * rstd * lnw[ch] + lnb[ch];
        }
    }
    for (int i = tid; i < 96 * 128; i += 256) {
        int kk = i % 96, j = i / 96;
        W_s[kk * 128 + j] = wproj[(oc * 128 + j) * 96 + kk];
    }
    __syncthreads();

    const int pg = tid & 7;
    const int og = tid >> 3;
    const float4* A4 = (const float4*)A_s;
    const float4* W4 = (const float4*)W_s;

    float acc[4][8];
    #pragma unroll
    for (int a = 0; a < 4; a++)
        #pragma unroll
        for (int b = 0; b < 8; b++) acc[a][b] = 0.f;

    #pragma unroll 4
    for (int kk = 0; kk < 96; kk++) {
        float4 a0 = A4[kk * 16 + pg * 2];
        float4 a1 = A4[kk * 16 + pg * 2 + 1];
        float4 w  = W4[kk * 32 + og];
        float ws4[4] = {w.x, w.y, w.z, w.w};
        float as8[8] = {a0.x, a0.y, a0.z, a0.w, a1.x, a1.y, a1.z, a1.w};
        #pragma unroll
        for (int jj = 0; jj < 4; jj++)
            #pragma unroll
            for (int pi = 0; pi < 8; pi++)
                acc[jj][pi] = fmaf(ws4[jj], as8[pi], acc[jj][pi]);
    }

    #pragma unroll
    for (int jj = 0; jj < 4; jj++) {
        int jg = oc * 128 + og * 4 + jj;
        #pragma unroll
        for (int pi = 0; pi < 8; pi++) {
            int pix = pix0 + pg * 8 + pi;
            float v = acc[jj][pi];
            if (jg < DIN) {
                int b = pix >> 12, l = pix & 4095;
                g_xm[(size_t)(b * DIN + jg) * LSEQ + l] = v;
            } else {
                g_zs[(size_t)pix * DIN + (jg - DIN)] = silu_f(v);
            }
        }
    }
}

// ================= K2: depthwise conv + silu =================
__global__ void k2_conv(const float* __restrict__ cw, const float* __restrict__ cb)
{
    int idx = blockIdx.x * 256 + threadIdx.x;
    int w_ = idx & 63, h_ = (idx >> 6) & 63;
    int t  = idx >> 12;
    int d  = t % DIN, b = t / DIN;
    const float* src = g_xm + (size_t)(b * DIN + d) * LSEQ;
    float acc = cb[d];
    #pragma unroll
    for (int dy = 0; dy < 3; dy++) {
        int hh = h_ + dy - 1;
        if (hh < 0 || hh > 63) continue;
        #pragma unroll
        for (int dx = 0; dx < 3; dx++) {
            int ww = w_ + dx - 1;
            if (ww < 0 || ww > 63) continue;
            acc = fmaf(src[hh * 64 + ww], cw[d * 9 + dy * 3 + dx], acc);
        }
    }
    float v = silu_f(acc);
    g_x0[idx] = v;
    g_x1[(size_t)(b * DIN + d) * LSEQ + w_ * 64 + h_] = v;
}

// ================= K3: x_proj + dt_proj + softplus =================
__global__ void k3_xproj(const float* __restrict__ xpw, const float* __restrict__ dtw,
                         const float* __restrict__ dtb)
{
    extern __shared__ float sm[];
    float* u_s  = sm;                         // 192*64
    float* wp_t = u_s + 192 * 64;             // 192*48 (transposed, row-padded)
    float* xd_s = wp_t + 192 * 48;            // 38*65
    float* dw_s = xd_s + 38 * 65;             // 192*6
    const int tid = threadIdx.x;
    const int bk = blockIdx.x >> 6;
    const int b = bk >> 2, k = bk & 3;
    const int l0 = (blockIdx.x & 63) << 6;
    const float* seq = (k & 1) ? g_x1 : g_x0;

    for (int i = tid; i < 192 * 48; i += 256) wp_t[i] = 0.f;
    __syncthreads();

    for (int i = tid; i < 192 * 64; i += 256) {
        int d = i >> 6, c = i & 63;
        u_s[i] = seq[(size_t)(b * DIN + d) * LSEQ + l0 + c];
    }
    for (int i = tid; i < 38 * 192; i += 256) {
        int kk = i % 192, row = i / 192;
        wp_t[kk * 48 + row] = xpw[k * 38 * 192 + i];
    }
    for (int i = tid; i < 192 * 6;  i += 256) dw_s[i] = dtw[k * 192 * 6 + i];
    __syncthreads();

    const int col = tid & 63, grp = tid >> 6;  // thread: 12 contiguous rows x 1 col
    float acc[12];
    #pragma unroll
    for (int j = 0; j < 12; j++) acc[j] = 0.f;
    const float4* wp4 = (const float4*)wp_t;
    #pragma unroll 2
    for (int kk = 0; kk < 192; kk++) {
        float uv = u_s[kk * 64 + col];
        float4 w0 = wp4[kk * 12 + grp * 3 + 0];
        float4 w1 = wp4[kk * 12 + grp * 3 + 1];
        float4 w2 = wp4[kk * 12 + grp * 3 + 2];
        acc[0]  = fmaf(w0.x, uv, acc[0]);  acc[1]  = fmaf(w0.y, uv, acc[1]);
        acc[2]  = fmaf(w0.z, uv, acc[2]);  acc[3]  = fmaf(w0.w, uv, acc[3]);
        acc[4]  = fmaf(w1.x, uv, acc[4]);  acc[5]  = fmaf(w1.y, uv, acc[5]);
        acc[6]  = fmaf(w1.z, uv, acc[6]);  acc[7]  = fmaf(w1.w, uv, acc[7]);
        acc[8]  = fmaf(w2.x, uv, acc[8]);  acc[9]  = fmaf(w2.y, uv, acc[9]);
        acc[10] = fmaf(w2.z, uv, acc[10]); acc[11] = fmaf(w2.w, uv, acc[11]);
    }
    #pragma unroll
    for (int j = 0; j < 12; j++) {
        int row = grp * 12 + j;
        if (row < 38) xd_s[row * 65 + col] = acc[j];
    }
    __syncthreads();

    const size_t bcbase = (size_t)(b * 4 + k) * LSEQ + l0;
    // B-only layout for k4a (rows 6..21)
    for (int i = tid; i < 16 * 64; i += 256) {
        int n = i & 15, cc = i >> 4;
        g_bb[(bcbase + cc) * 16 + n] = xd_s[(6 + n) * 65 + cc];
    }
    // interleaved (B,C) float4 layout for k4c
    for (int i = tid; i < 8 * 64; i += 256) {
        int n8 = i & 7, cc = i >> 3;
        float4 v;
        v.x = xd_s[(6  + n8) * 65 + cc];   // B_{n8}
        v.y = xd_s[(22 + n8) * 65 + cc];   // C_{n8}
        v.z = xd_s[(14 + n8) * 65 + cc];   // B_{n8+8}
        v.w = xd_s[(30 + n8) * 65 + cc];   // C_{n8+8}
        g_bc4[(bcbase + cc) * 8 + n8] = v;
    }
    const int dg = tid >> 6;
    const size_t dbase = (size_t)(b * 4 + k) * DIN * LSEQ;
    for (int j = 0; j < 48; j++) {
        int d = dg + 4 * j;
        float val = dtb[k * DIN + d];
        #pragma unroll
        for (int r = 0; r < 6; r++)
            val = fmaf(dw_s[d * 6 + r], xd_s[r * 65 + col], val);
        val = fmaxf(val, 0.f) + log1pf(__expf(-fabsf(val)));
        g_delta[dbase + (size_t)d * LSEQ + l0 + col] = val;
    }
}

// ================= K4a: local chunk scan =================
template<bool REV>
__device__ __forceinline__ void k4a_body(const int K0, const float* __restrict__ alog)
{
    const int lane = threadIdx.x & 31;
    const int w = blockIdx.x * 8 + (threadIdx.x >> 5);   // 0..6143
    const int chunk = w & (NCHUNK - 1);
    const int pair  = w >> 4;                            // 0..383
    const int half = lane >> 4, n = lane & 15;
    const int kk = pair / 192;
    const int rem = pair - kk * 192;
    const int b = rem / 96;
    const int d = (rem - b * 96) * 2 + half;
    const int k = K0 + kk;
    const int bk = b * 4 + k;
    const int ch = bk * DIN + d;
    const float An2 = -__expf(alog[(k * DIN + d) * NST + n]) * 1.44269504f;

    const float* dptr = g_delta + ((size_t)bk * DIN + d) * LSEQ;
    const float* uptr = (kk ? g_x1 : g_x0) + ((size_t)b * DIN + d) * LSEQ;
    const float* bptr = g_bb + (size_t)bk * LSEQ * 16 + n;

    float h = 0.f, sdel = 0.f;
    if (!REV) {
        const int i0 = chunk * CLEN;
        const float4* dp4 = (const float4*)(dptr + i0);
        const float4* up4 = (const float4*)(uptr + i0);
        const float* bp = bptr + (size_t)i0 * 16;
        #pragma unroll 4
        for (int s = 0; s < CLEN / 4; s++) {
            float4 d4 = dp4[s]; float4 u4 = up4[s];
            float dd[4] = {d4.x, d4.y, d4.z, d4.w};
            float uu[4] = {u4.x, u4.y, u4.z, u4.w};
            #pragma unroll
            for (int j = 0; j < 4; j++) {
                float Bv = __ldg(bp + (s * 4 + j) * 16);
                float a = exp2f(dd[j] * An2);
                h = fmaf(a, h, dd[j] * uu[j] * Bv);
                sdel += dd[j];
            }
        }
    } else {
        const int ltop = LSEQ - chunk * CLEN;
        const float4* dp4 = (const float4*)(dptr + ltop) - 1;
        const float4* up4 = (const float4*)(uptr + ltop) - 1;
        const float* bp = bptr + (size_t)(ltop - 1) * 16;
        #pragma unroll 4
        for (int s = 0; s < CLEN / 4; s++) {
            float4 d4 = dp4[-s]; float4 u4 = up4[-s];
            float dd[4] = {d4.x, d4.y, d4.z, d4.w};
            float uu[4] = {u4.x, u4.y, u4.z, u4.w};
            #pragma unroll
            for (int j = 0; j < 4; j++) {
                const int e = 3 - j;
                float Bv = __ldg(bp - (s * 4 + j) * 16);
                float a = exp2f(dd[e] * An2);
                h = fmaf(a, h, dd[e] * uu[e] * Bv);
                sdel += dd[e];
            }
        }
    }
    g_P [(ch * NCHUNK + chunk) * NST + n] = exp2f(An2 * sdel);
    g_he[(ch * NCHUNK + chunk) * NST + n] = h;
}

__global__ void k4a_scan(const float* __restrict__ alog)
{
    if (blockIdx.y == 0) k4a_body<false>(0, alog);
    else                 k4a_body<true >(2, alog);
}

// ================= K4b: carry across chunks =================
__global__ void k4b_carry()
{
    int idx = blockIdx.x * 256 + threadIdx.x;   // 0..24575
    int ch = idx >> 4, n = idx & 15;
    float H = 0.f;
    #pragma unroll
    for (int c = 0; c < NCHUNK; c++) {
        int o = (ch * NCHUNK + c) * NST + n;
        g_H[o] = H;
        H = fmaf(g_P[o], H, g_he[o]);
    }
}

// ================= K4c: seeded scan, emit y (natural order, float4 stores) ======
template<bool REV>
__device__ __forceinline__ void k4c_body(const int K0, const float* __restrict__ alog,
                                         const float* __restrict__ ds)
{
    const int lane = threadIdx.x & 31;
    const int w = blockIdx.x * 8 + (threadIdx.x >> 5);   // 0..3071
    const int chunk = w & (NCHUNK - 1);
    const int quad  = w >> 4;                            // 0..191
    const int c2 = lane >> 3;
    const int n0 = lane & 7;
    const int kk = quad / 96;
    const int rem = quad - kk * 96;
    const int b = rem / 48;
    const int d = (rem - b * 48) * 4 + c2;
    const int k = K0 + kk;
    const int bk = b * 4 + k;
    const int ch = bk * DIN + d;

    const float An0 = -__expf(alog[(k * DIN + d) * NST + n0]) * 1.44269504f;
    const float An1 = -__expf(alog[(k * DIN + d) * NST + n0 + 8]) * 1.44269504f;
    const float Dd = ds[k * DIN + d];

    const float* dptr = g_delta + ((size_t)bk * DIN + d) * LSEQ;
    const float* uptr = (kk ? g_x1 : g_x0) + ((size_t)b * DIN + d) * LSEQ;
    const float4* bcp = g_bc4 + (size_t)bk * LSEQ * 8 + n0;
    float* yp = g_y + ((size_t)(k * BATCH + b) * DIN + d) * LSEQ;

    float h0 = g_H[(ch * NCHUNK + chunk) * NST + n0];
    float h1 = g_H[(ch * NCHUNK + chunk) * NST + n0 + 8];

    if (!REV) {
        const int i0 = chunk * CLEN;
        const float4* dp4 = (const float4*)(dptr + i0);
        const float4* up4 = (const float4*)(uptr + i0);
        const float4* bp = bcp + (size_t)i0 * 8;
        float4* yp4 = (float4*)(yp + i0);
        #pragma unroll 2
        for (int s = 0; s < CLEN / 4; s++) {
            float4 dv = dp4[s]; float4 uv = up4[s];
            float dd[4] = {dv.x, dv.y, dv.z, dv.w};
            float uu[4] = {uv.x, uv.y, uv.z, uv.w};
            float tr[4];
            #pragma unroll
            for (int j = 0; j < 4; j++) {
                float4 bc = __ldg(bp + (s * 4 + j) * 8);
                float du = dd[j] * uu[j];
                float a0 = exp2f(dd[j] * An0);
                float a1 = exp2f(dd[j] * An1);
                h0 = fmaf(a0, h0, du * bc.x);
                h1 = fmaf(a1, h1, du * bc.z);
                float t = fmaf(h1, bc.w, h0 * bc.y);
                t += __shfl_xor_sync(0xffffffffu, t, 4);
                t += __shfl_xor_sync(0xffffffffu, t, 2);
                t += __shfl_xor_sync(0xffffffffu, t, 1);
                tr[j] = fmaf(Dd, uu[j], t);
            }
            if (n0 == 0) yp4[s] = make_float4(tr[0], tr[1], tr[2], tr[3]);
        }
    } else {
        const int ltop = LSEQ - chunk * CLEN;
        const float4* dp4 = (const float4*)(dptr + ltop) - 1;
        const float4* up4 = (const float4*)(uptr + ltop) - 1;
        const float4* bp = bcp + (size_t)(ltop - 1) * 8;
        float4* yp4 = (float4*)(yp + ltop) - 1;
        #pragma unroll 2
        for (int s = 0; s < CLEN / 4; s++) {
            float4 dv = dp4[-s]; float4 uv = up4[-s];
            float dd[4] = {dv.x, dv.y, dv.z, dv.w};
            float uu[4] = {uv.x, uv.y, uv.z, uv.w};
            float tr[4];
            #pragma unroll
            for (int j = 0; j < 4; j++) {
                const int e = 3 - j;
                float4 bc = __ldg(bp - (s * 4 + j) * 8);
                float du = dd[e] * uu[e];
                float a0 = exp2f(dd[e] * An0);
                float a1 = exp2f(dd[e] * An1);
                h0 = fmaf(a0, h0, du * bc.x);
                h1 = fmaf(a1, h1, du * bc.z);
                float t = fmaf(h1, bc.w, h0 * bc.y);
                t += __shfl_xor_sync(0xffffffffu, t, 4);
                t += __shfl_xor_sync(0xffffffffu, t, 2);
                t += __shfl_xor_sync(0xffffffffu, t, 1);
                tr[e] = fmaf(Dd, uu[e], t);
            }
            if (n0 == 0) yp4[-s] = make_float4(tr[0], tr[1], tr[2], tr[3]);
        }
    }
}

__global__ void k4c_scan(const float* __restrict__ alog, const float* __restrict__ ds)
{
    if (blockIdx.y == 0) k4c_body<false>(0, alog, ds);
    else                 k4c_body<true >(2, alog, ds);
}

// ================= K4t: transpose wh planes + merge all 4 into g_ysum =========
__global__ void k4t_merge()
{
    __shared__ float s1[64 * 65];
    __shared__ float s3[64 * 65];
    const int tid = threadIdx.x;
    const int b = blockIdx.x / DIN;
    const int d = blockIdx.x % DIN;
    const float4* p0 = (const float4*)(g_y + ((size_t)(0 * BATCH + b) * DIN + d) * LSEQ);
    const float4* p1 = (const float4*)(g_y + ((size_t)(1 * BATCH + b) * DIN + d) * LSEQ);
    const float4* p2 = (const float4*)(g_y + ((size_t)(2 * BATCH + b) * DIN + d) * LSEQ);
    const float4* p3 = (const float4*)(g_y + ((size_t)(3 * BATCH + b) * DIN + d) * LSEQ);

    // wh planes stored in x1-order: index i = w*64 + h; canonical pos = h*64 + w
    for (int t4 = tid; t4 < 1024; t4 += 256) {
        int i = t4 * 4;
        int w_ = i >> 6, h0 = i & 63;
        float4 v1 = p1[t4], v3 = p3[t4];
        s1[(h0 + 0) * 65 + w_] = v1.x; s1[(h0 + 1) * 65 + w_] = v1.y;
        s1[(h0 + 2) * 65 + w_] = v1.z; s1[(h0 + 3) * 65 + w_] = v1.w;
        s3[(h0 + 0) * 65 + w_] = v3.x; s3[(h0 + 1) * 65 + w_] = v3.y;
        s3[(h0 + 2) * 65 + w_] = v3.z; s3[(h0 + 3) * 65 + w_] = v3.w;
    }
    __syncthreads();

    float4* po = (float4*)(g_ysum + (size_t)(b * DIN + d) * LSEQ);
    for (int t4 = tid; t4 < 1024; t4 += 256) {
        int j = t4 * 4;
        int h = j >> 6, w0 = j & 63;
        float4 a = p0[t4], c = p2[t4];
        float4 r;
        r.x = a.x + c.x + s1[h * 65 + w0 + 0] + s3[h * 65 + w0 + 0];
        r.y = a.y + c.y + s1[h * 65 + w0 + 1] + s3[h * 65 + w0 + 1];
        r.z = a.z + c.z + s1[h * 65 + w0 + 2] + s3[h * 65 + w0 + 2];
        r.w = a.w + c.w + s1[h * 65 + w0 + 3] + s3[h * 65 + w0 + 3];
        po[t4] = r;
    }
}

// ================= K5: out-LN + gate + out_proj + residual =================
__global__ void k5_final(const float* __restrict__ onw, const float* __restrict__ onb,
                         const float* __restrict__ wout, float* __restrict__ out)
{
    extern __shared__ float sm[];
    float* yc = sm;                  // 192*36
    float* ws = sm + 192 * 36;       // 96*192
    const int tid = threadIdx.x, lane = tid & 31, warp = tid >> 5;
    const int b = blockIdx.x >> 7;
    const int l0 = (blockIdx.x & 127) << 5;

    for (int i = tid; i < 192 * 32; i += 256) {
        int d = i >> 5, p = i & 31;
        yc[d * 36 + p] = g_ysum[(size_t)(b * DIN + d) * LSEQ + l0 + p];
    }
    for (int i = tid; i < 96 * 192; i += 256) ws[i] = wout[i];
    __syncthreads();

    #pragma unroll
    for (int pp = 0; pp < 4; pp++) {
        const int p = warp * 4 + pp;
        float s = 0.f, s2 = 0.f, vv[6];
        #pragma unroll
        for (int j = 0; j < 6; j++) {
            float v = yc[(lane + 32 * j) * 36 + p];
            vv[j] = v; s += v; s2 += v * v;
        }
        #pragma unroll
        for (int o = 16; o > 0; o >>= 1) {
            s  += __shfl_xor_sync(0xffffffffu, s,  o);
            s2 += __shfl_xor_sync(0xffffffffu, s2, o);
        }
        float mu = s * (1.f / 192.f);
        float var = s2 * (1.f / 192.f) - mu * mu;
        float rstd = rsqrtf(var + 1e-5f);
        size_t zbase = ((size_t)(b * LSEQ + l0 + p)) * DIN;
        #pragma unroll
        for (int j = 0; j < 6; j++) {
            int dd = lane + 32 * j;
            float g = (vv[j] - mu) * rstd * onw[dd] + onb[dd];
            yc[dd * 36 + p] = g * g_zs[zbase + dd];
        }
    }
    __syncthreads();

    const int og = tid >> 3;
    const int pg = tid & 7;
    float acc[3][4];
    #pragma unroll
    for (int a = 0; a < 3; a++)
        #pragma unroll
        for (int c = 0; c < 4; c++) acc[a][c] = 0.f;

    #pragma unroll 4
    for (int dd = 0; dd < 192; dd++) {
        float4 gv = *(const float4*)&yc[dd * 36 + pg * 4];
        float g4[4] = {gv.x, gv.y, gv.z, gv.w};
        #pragma unroll
        for (int oi = 0; oi < 3; oi++) {
            float w2 = ws[(og * 3 + oi) * 192 + dd];
            #pragma unroll
            for (int pi = 0; pi < 4; pi++)
                acc[oi][pi] = fmaf(w2, g4[pi], acc[oi][pi]);
        }
    }
    #pragma unroll
    for (int oi = 0; oi < 3; oi++)
        #pragma unroll
        for (int pi = 0; pi < 4; pi++) {
            int o = og * 3 + oi;
            size_t pix = (size_t)b * LSEQ + l0 + pg * 4 + pi;
            out[pix * 96 + o] = g_diff[pix * 96 + o] + acc[oi][pi];
        }
}

// ================= launch =================
extern "C" void kernel_launch(void* const* d_in, const int* in_sizes, int n_in,
                              void* d_out, int out_size)
{
    const float* x     = (const float*)d_in[0];
    const float* y     = (const float*)d_in[1];
    const float* ln_w  = (const float*)d_in[2];
    const float* ln_b  = (const float*)d_in[3];
    const float* ipw   = (const float*)d_in[4];
    const float* cw    = (const float*)d_in[5];
    const float* cb    = (const float*)d_in[6];
    const float* xpw   = (const float*)d_in[7];
    const float* dtw   = (const float*)d_in[8];
    const float* dtb   = (const float*)d_in[9];
    const float* alog  = (const float*)d_in[10];
    const float* ds    = (const float*)d_in[11];
    const float* onw   = (const float*)d_in[12];
    const float* onb   = (const float*)d_in[13];
    const float* wout  = (const float*)d_in[14];
    float* out = (float*)d_out;

    const int smem1 = (96 * 64 + 96 * 128) * 4;
    const int smem3 = (192 * 64 + 192 * 48 + 38 * 65 + 192 * 6) * 4;
    const int smem5 = (192 * 36 + 96 * 192) * 4;
    cudaFuncSetAttribute(k1_prologue, cudaFuncAttributeMaxDynamicSharedMemorySize, smem1);
    cudaFuncSetAttribute(k3_xproj,   cudaFuncAttributeMaxDynamicSharedMemorySize, smem3);
    cudaFuncSetAttribute(k5_final,   cudaFuncAttributeMaxDynamicSharedMemorySize, smem5);

    k1_prologue<<<dim3(128, 3), 256, smem1>>>(x, y, ln_w, ln_b, ipw);
    k2_conv<<<(BATCH * DIN * LSEQ) / 256, 256>>>(cw, cb);
    k3_xproj<<<BATCH * 4 * (LSEQ / 64), 256, smem3>>>(xpw, dtw, dtb);
    k4a_scan<<<dim3(768, 2), 256>>>(alog);
    k4b_carry<<<NCH * NST / 256, 256>>>();
    k4c_scan<<<dim3(384, 2), 256>>>(alog, ds);
    k4t_merge<<<BATCH * DIN, 256>>>();
    k5_final<<<BATCH * (LSEQ / 32), 256, smem5>>>(onw, onb, wout, out);
}

// round 7
// speedup vs baseline: 3.2192x; 1.0327x over previous
#include <cuda_runtime.h>
#include <math.h>

#define BATCH 2
#define CDIM  96
#define DIN   192
#define NST   16
#define LSEQ  4096
#define NPIX  (BATCH*LSEQ)
#define NCH   (BATCH*4*DIN)     // 1536 scan channels
#define NCHUNK 16
#define CLEN  (LSEQ/NCHUNK)     // 256

// ---------------- persistent device scratch ----------------
__device__ float  g_diff [NPIX*CDIM];
__device__ float  g_zs   [NPIX*DIN];
__device__ float  g_xm   [BATCH*DIN*LSEQ];
__device__ float  g_x0   [BATCH*DIN*LSEQ];
__device__ float  g_x1   [BATCH*DIN*LSEQ];
__device__ float  g_delta[BATCH*4*DIN*LSEQ];
__device__ float4 g_bb4  [BATCH*4*(LSEQ/4)*16]; // B[n] grouped by 4 consecutive l
__device__ float4 g_bc4  [BATCH*4*LSEQ*8];      // (B_n, C_n, B_{n+8}, C_{n+8})
__device__ float  g_y    [4*BATCH*DIN*LSEQ];    // per-direction y, scan-native order
__device__ float  g_ysum [BATCH*DIN*LSEQ];      // merged y, canonical row-major
__device__ float  g_P    [NCH*NCHUNK*NST];
__device__ float  g_he   [NCH*NCHUNK*NST];
__device__ float  g_H    [NCH*NCHUNK*NST];

__device__ __forceinline__ float silu_f(float v){ return v / (1.f + __expf(-v)); }

// ================= K1: diff + LN + in_proj GEMM =================
__global__ void k1_prologue(const float* __restrict__ x, const float* __restrict__ y,
                            const float* __restrict__ lnw, const float* __restrict__ lnb,
                            const float* __restrict__ wproj)
{
    extern __shared__ float sm[];
    float* A_s = sm;            // 96*64
    float* W_s = sm + 96*64;    // 96*128
    const int tid = threadIdx.x, lane = tid & 31, warp = tid >> 5;
    const int pix0 = blockIdx.x * 64;
    const int oc = blockIdx.y;

    for (int pp = 0; pp < 8; pp++) {
        const int p = warp * 8 + pp;
        const int base = (pix0 + p) * CDIM;
        float vv[3]; float s = 0.f, s2 = 0.f;
        #pragma unroll
        for (int j = 0; j < 3; j++) {
            int ch = lane + 32 * j;
            float d = fabsf(x[base + ch] - y[base + ch]);
            if (oc == 0) g_diff[base + ch] = d;
            vv[j] = d; s += d; s2 += d * d;
        }
        #pragma unroll
        for (int o = 16; o > 0; o >>= 1) {
            s  += __shfl_xor_sync(0xffffffffu, s,  o);
            s2 += __shfl_xor_sync(0xffffffffu, s2, o);
        }
        float mu = s * (1.f / 96.f);
        float var = s2 * (1.f / 96.f) - mu * mu;
        float rstd = rsqrtf(var + 1e-5f);
        #pragma unroll
        for (int j = 0; j < 3; j++) {
            int ch = lane + 32 * j;
            A_s[ch * 64 + p] = (vv[j] - mu) * rstd * lnw[ch] + lnb[ch];
        }
    }
    for (int i = tid; i < 96 * 128; i += 256) {
        int kk = i % 96, j = i / 96;
        W_s[kk * 128 + j] = wproj[(oc * 128 + j) * 96 + kk];
    }
    __syncthreads();

    const int pg = tid & 7;
    const int og = tid >> 3;
    const float4* A4 = (const float4*)A_s;
    const float4* W4 = (const float4*)W_s;

    float acc[4][8];
    #pragma unroll
    for (int a = 0; a < 4; a++)
        #pragma unroll
        for (int b = 0; b < 8; b++) acc[a][b] = 0.f;

    #pragma unroll 4
    for (int kk = 0; kk < 96; kk++) {
        float4 a0 = A4[kk * 16 + pg * 2];
        float4 a1 = A4[kk * 16 + pg * 2 + 1];
        float4 w  = W4[kk * 32 + og];
        float ws4[4] = {w.x, w.y, w.z, w.w};
        float as8[8] = {a0.x, a0.y, a0.z, a0.w, a1.x, a1.y, a1.z, a1.w};
        #pragma unroll
        for (int jj = 0; jj < 4; jj++)
            #pragma unroll
            for (int pi = 0; pi < 8; pi++)
                acc[jj][pi] = fmaf(ws4[jj], as8[pi], acc[jj][pi]);
    }

    // vectorized stores
    const int jg0 = oc * 128 + og * 4;                 // first of 4 outs (uniform per thread)
    const int pixb = pix0 + pg * 8;
    const int bb = pixb >> 12, lb = pixb & 4095;
    if (jg0 + 3 < DIN) {
        #pragma unroll
        for (int jj = 0; jj < 4; jj++) {
            float* row = g_xm + (size_t)(bb * DIN + jg0 + jj) * LSEQ + lb;
            *(float4*)row       = make_float4(acc[jj][0], acc[jj][1], acc[jj][2], acc[jj][3]);
            *(float4*)(row + 4) = make_float4(acc[jj][4], acc[jj][5], acc[jj][6], acc[jj][7]);
        }
    } else {
        const int zc = jg0 - DIN;
        #pragma unroll
        for (int pi = 0; pi < 8; pi++) {
            float* zp = g_zs + (size_t)(pixb + pi) * DIN + zc;
            *(float4*)zp = make_float4(silu_f(acc[0][pi]), silu_f(acc[1][pi]),
                                       silu_f(acc[2][pi]), silu_f(acc[3][pi]));
        }
    }
}

// ================= K2: depthwise conv + silu =================
__global__ void k2_conv(const float* __restrict__ cw, const float* __restrict__ cb)
{
    int idx = blockIdx.x * 256 + threadIdx.x;
    int w_ = idx & 63, h_ = (idx >> 6) & 63;
    int t  = idx >> 12;
    int d  = t % DIN, b = t / DIN;
    const float* src = g_xm + (size_t)(b * DIN + d) * LSEQ;
    float acc = cb[d];
    #pragma unroll
    for (int dy = 0; dy < 3; dy++) {
        int hh = h_ + dy - 1;
        if (hh < 0 || hh > 63) continue;
        #pragma unroll
        for (int dx = 0; dx < 3; dx++) {
            int ww = w_ + dx - 1;
            if (ww < 0 || ww > 63) continue;
            acc = fmaf(src[hh * 64 + ww], cw[d * 9 + dy * 3 + dx], acc);
        }
    }
    float v = silu_f(acc);
    g_x0[idx] = v;
    g_x1[(size_t)(b * DIN + d) * LSEQ + w_ * 64 + h_] = v;
}

// ================= K3: x_proj + dt_proj + softplus =================
__global__ void k3_xproj(const float* __restrict__ xpw, const float* __restrict__ dtw,
                         const float* __restrict__ dtb)
{
    extern __shared__ float sm[];
    float* u_s  = sm;                         // 192*64
    float* wp_t = u_s + 192 * 64;             // 192*48 (transposed, row-padded)
    float* xd_s = wp_t + 192 * 48;            // 38*65
    float* dw_s = xd_s + 38 * 65;             // 192*6
    const int tid = threadIdx.x;
    const int bk = blockIdx.x >> 6;
    const int b = bk >> 2, k = bk & 3;
    const int l0 = (blockIdx.x & 63) << 6;
    const float* seq = (k & 1) ? g_x1 : g_x0;

    for (int i = tid; i < 192 * 48; i += 256) wp_t[i] = 0.f;
    __syncthreads();

    for (int i = tid; i < 192 * 64; i += 256) {
        int d = i >> 6, c = i & 63;
        u_s[i] = seq[(size_t)(b * DIN + d) * LSEQ + l0 + c];
    }
    for (int i = tid; i < 38 * 192; i += 256) {
        int kk = i % 192, row = i / 192;
        wp_t[kk * 48 + row] = xpw[k * 38 * 192 + i];
    }
    for (int i = tid; i < 192 * 6;  i += 256) dw_s[i] = dtw[k * 192 * 6 + i];
    __syncthreads();

    const int col = tid & 63, grp = tid >> 6;
    float acc[12];
    #pragma unroll
    for (int j = 0; j < 12; j++) acc[j] = 0.f;
    const float4* wp4 = (const float4*)wp_t;
    #pragma unroll 2
    for (int kk = 0; kk < 192; kk++) {
        float uv = u_s[kk * 64 + col];
        float4 w0 = wp4[kk * 12 + grp * 3 + 0];
        float4 w1 = wp4[kk * 12 + grp * 3 + 1];
        float4 w2 = wp4[kk * 12 + grp * 3 + 2];
        acc[0]  = fmaf(w0.x, uv, acc[0]);  acc[1]  = fmaf(w0.y, uv, acc[1]);
        acc[2]  = fmaf(w0.z, uv, acc[2]);  acc[3]  = fmaf(w0.w, uv, acc[3]);
        acc[4]  = fmaf(w1.x, uv, acc[4]);  acc[5]  = fmaf(w1.y, uv, acc[5]);
        acc[6]  = fmaf(w1.z, uv, acc[6]);  acc[7]  = fmaf(w1.w, uv, acc[7]);
        acc[8]  = fmaf(w2.x, uv, acc[8]);  acc[9]  = fmaf(w2.y, uv, acc[9]);
        acc[10] = fmaf(w2.z, uv, acc[10]); acc[11] = fmaf(w2.w, uv, acc[11]);
    }
    #pragma unroll
    for (int j = 0; j < 12; j++) {
        int row = grp * 12 + j;
        if (row < 38) xd_s[row * 65 + col] = acc[j];
    }
    __syncthreads();

    // B-only layout for k4a: g_bb4[(bk*1024 + lblk)*16 + n].component[l%4]
    const size_t lb4 = (size_t)bk * 1024 + (l0 >> 2);
    for (int i = tid; i < 16 * 64; i += 256) {
        int n = i & 15, cc = i >> 4;
        ((float*)g_bb4)[((lb4 + (cc >> 2)) * 16 + n) * 4 + (cc & 3)] = xd_s[(6 + n) * 65 + cc];
    }
    // interleaved (B,C) float4 layout for k4c
    const size_t bcbase = (size_t)bk * LSEQ + l0;
    for (int i = tid; i < 8 * 64; i += 256) {
        int n8 = i & 7, cc = i >> 3;
        float4 v;
        v.x = xd_s[(6  + n8) * 65 + cc];   // B_{n8}
        v.y = xd_s[(22 + n8) * 65 + cc];   // C_{n8}
        v.z = xd_s[(14 + n8) * 65 + cc];   // B_{n8+8}
        v.w = xd_s[(30 + n8) * 65 + cc];   // C_{n8+8}
        g_bc4[(bcbase + cc) * 8 + n8] = v;
    }
    const int dg = tid >> 6;
    const size_t dbase = (size_t)bk * DIN * LSEQ;
    for (int j = 0; j < 48; j++) {
        int d = dg + 4 * j;
        float val = dtb[k * DIN + d];
        #pragma unroll
        for (int r = 0; r < 6; r++)
            val = fmaf(dw_s[d * 6 + r], xd_s[r * 65 + col], val);
        val = fmaxf(val, 0.f) + log1pf(__expf(-fabsf(val)));
        g_delta[dbase + (size_t)d * LSEQ + l0 + col] = val;
    }
}

// ================= K4a: local chunk scan =================
template<bool REV>
__device__ __forceinline__ void k4a_body(const int K0, const float* __restrict__ alog)
{
    const int lane = threadIdx.x & 31;
    const int w = blockIdx.x * 8 + (threadIdx.x >> 5);   // 0..6143
    const int chunk = w & (NCHUNK - 1);
    const int pair  = w >> 4;                            // 0..383
    const int half = lane >> 4, n = lane & 15;
    const int kk = pair / 192;
    const int rem = pair - kk * 192;
    const int b = rem / 96;
    const int d = (rem - b * 96) * 2 + half;
    const int k = K0 + kk;
    const int bk = b * 4 + k;
    const int ch = bk * DIN + d;
    const float An2 = -__expf(alog[(k * DIN + d) * NST + n]) * 1.44269504f;

    const float* dptr = g_delta + ((size_t)bk * DIN + d) * LSEQ;
    const float* uptr = (kk ? g_x1 : g_x0) + ((size_t)b * DIN + d) * LSEQ;
    const float4* bp4 = g_bb4 + (size_t)bk * 1024 * 16 + n;  // step by lblk*16

    float h = 0.f, sdel = 0.f;
    if (!REV) {
        const int i0 = chunk * CLEN;
        const float4* dp4 = (const float4*)(dptr + i0);
        const float4* up4 = (const float4*)(uptr + i0);
        const float4* bb = bp4 + (size_t)(i0 >> 2) * 16;
        #pragma unroll 4
        for (int s = 0; s < CLEN / 4; s++) {
            float4 d4 = dp4[s]; float4 u4 = up4[s];
            float4 b4 = __ldg(bb + s * 16);
            float dd[4] = {d4.x, d4.y, d4.z, d4.w};
            float uu[4] = {u4.x, u4.y, u4.z, u4.w};
            float bv[4] = {b4.x, b4.y, b4.z, b4.w};
            sdel += (dd[0] + dd[1]) + (dd[2] + dd[3]);
            #pragma unroll
            for (int j = 0; j < 4; j++) {
                float a = exp2f(dd[j] * An2);
                h = fmaf(a, h, dd[j] * uu[j] * bv[j]);
            }
        }
    } else {
        const int ltop = LSEQ - chunk * CLEN;
        const float4* dp4 = (const float4*)(dptr + ltop) - 1;
        const float4* up4 = (const float4*)(uptr + ltop) - 1;
        const float4* bb = bp4 + (size_t)((ltop >> 2) - 1) * 16;
        #pragma unroll 4
        for (int s = 0; s < CLEN / 4; s++) {
            float4 d4 = dp4[-s]; float4 u4 = up4[-s];
            float4 b4 = __ldg(bb - s * 16);
            float dd[4] = {d4.x, d4.y, d4.z, d4.w};
            float uu[4] = {u4.x, u4.y, u4.z, u4.w};
            float bv[4] = {b4.x, b4.y, b4.z, b4.w};
            sdel += (dd[0] + dd[1]) + (dd[2] + dd[3]);
            #pragma unroll
            for (int j = 0; j < 4; j++) {
                const int e = 3 - j;
                float a = exp2f(dd[e] * An2);
                h = fmaf(a, h, dd[e] * uu[e] * bv[e]);
            }
        }
    }
    g_P [(ch * NCHUNK + chunk) * NST + n] = exp2f(An2 * sdel);
    g_he[(ch * NCHUNK + chunk) * NST + n] = h;
}

__global__ void k4a_scan(const float* __restrict__ alog)
{
    if (blockIdx.y == 0) k4a_body<false>(0, alog);
    else                 k4a_body<true >(2, alog);
}

// ================= K4b: carry across chunks =================
__global__ void k4b_carry()
{
    int idx = blockIdx.x * 256 + threadIdx.x;   // 0..24575
    int ch = idx >> 4, n = idx & 15;
    float H = 0.f;
    #pragma unroll
    for (int c = 0; c < NCHUNK; c++) {
        int o = (ch * NCHUNK + c) * NST + n;
        g_H[o] = H;
        H = fmaf(g_P[o], H, g_he[o]);
    }
}

// ================= K4c: seeded scan, emit y (natural order, float4 stores) ======
template<bool REV>
__device__ __forceinline__ void k4c_body(const int K0, const float* __restrict__ alog,
                                         const float* __restrict__ ds)
{
    const int lane = threadIdx.x & 31;
    const int w = blockIdx.x * 8 + (threadIdx.x >> 5);   // 0..3071
    const int chunk = w & (NCHUNK - 1);
    const int quad  = w >> 4;                            // 0..191
    const int c2 = lane >> 3;
    const int n0 = lane & 7;
    const int kk = quad / 96;
    const int rem = quad - kk * 96;
    const int b = rem / 48;
    const int d = (rem - b * 48) * 4 + c2;
    const int k = K0 + kk;
    const int bk = b * 4 + k;
    const int ch = bk * DIN + d;

    const float An0 = -__expf(alog[(k * DIN + d) * NST + n0]) * 1.44269504f;
    const float An1 = -__expf(alog[(k * DIN + d) * NST + n0 + 8]) * 1.44269504f;
    const float Dd = ds[k * DIN + d];

    const float* dptr = g_delta + ((size_t)bk * DIN + d) * LSEQ;
    const float* uptr = (kk ? g_x1 : g_x0) + ((size_t)b * DIN + d) * LSEQ;
    const float4* bcp = g_bc4 + (size_t)bk * LSEQ * 8 + n0;
    float* yp = g_y + ((size_t)(k * BATCH + b) * DIN + d) * LSEQ;

    float h0 = g_H[(ch * NCHUNK + chunk) * NST + n0];
    float h1 = g_H[(ch * NCHUNK + chunk) * NST + n0 + 8];

    if (!REV) {
        const int i0 = chunk * CLEN;
        const float4* dp4 = (const float4*)(dptr + i0);
        const float4* up4 = (const float4*)(uptr + i0);
        const float4* bp = bcp + (size_t)i0 * 8;
        float4* yp4 = (float4*)(yp + i0);
        #pragma unroll 4
        for (int s = 0; s < CLEN / 4; s++) {
            float4 dv = dp4[s]; float4 uv = up4[s];
            float dd[4] = {dv.x, dv.y, dv.z, dv.w};
            float uu[4] = {uv.x, uv.y, uv.z, uv.w};
            float tr[4];
            #pragma unroll
            for (int j = 0; j < 4; j++) {
                float4 bc = __ldg(bp + (s * 4 + j) * 8);
                float du = dd[j] * uu[j];
                float a0 = exp2f(dd[j] * An0);
                float a1 = exp2f(dd[j] * An1);
                h0 = fmaf(a0, h0, du * bc.x);
                h1 = fmaf(a1, h1, du * bc.z);
                float t = fmaf(h1, bc.w, h0 * bc.y);
                t += __shfl_xor_sync(0xffffffffu, t, 4);
                t += __shfl_xor_sync(0xffffffffu, t, 2);
                t += __shfl_xor_sync(0xffffffffu, t, 1);
                tr[j] = fmaf(Dd, uu[j], t);
            }
            if (n0 == 0) yp4[s] = make_float4(tr[0], tr[1], tr[2], tr[3]);
        }
    } else {
        const int ltop = LSEQ - chunk * CLEN;
        const float4* dp4 = (const float4*)(dptr + ltop) - 1;
        const float4* up4 = (const float4*)(uptr + ltop) - 1;
        const float4* bp = bcp + (size_t)(ltop - 1) * 8;
        float4* yp4 = (float4*)(yp + ltop) - 1;
        #pragma unroll 4
        for (int s = 0; s < CLEN / 4; s++) {
            float4 dv = dp4[-s]; float4 uv = up4[-s];
            float dd[4] = {dv.x, dv.y, dv.z, dv.w};
            float uu[4] = {uv.x, uv.y, uv.z, uv.w};
            float tr[4];
            #pragma unroll
            for (int j = 0; j < 4; j++) {
                const int e = 3 - j;
                float4 bc = __ldg(bp - (s * 4 + j) * 8);
                float du = dd[e] * uu[e];
                float a0 = exp2f(dd[e] * An0);
                float a1 = exp2f(dd[e] * An1);
                h0 = fmaf(a0, h0, du * bc.x);
                h1 = fmaf(a1, h1, du * bc.z);
                float t = fmaf(h1, bc.w, h0 * bc.y);
                t += __shfl_xor_sync(0xffffffffu, t, 4);
                t += __shfl_xor_sync(0xffffffffu, t, 2);
                t += __shfl_xor_sync(0xffffffffu, t, 1);
                tr[e] = fmaf(Dd, uu[e], t);
            }
            if (n0 == 0) yp4[-s] = make_float4(tr[0], tr[1], tr[2], tr[3]);
        }
    }
}

__global__ void k4c_scan(const float* __restrict__ alog, const float* __restrict__ ds)
{
    if (blockIdx.y == 0) k4c_body<false>(0, alog, ds);
    else                 k4c_body<true >(2, alog, ds);
}

// ================= K4t: transpose wh planes + merge all 4 into g_ysum =========
__global__ void k4t_merge()
{
    __shared__ float s1[64 * 65];
    __shared__ float s3[64 * 65];
    const int tid = threadIdx.x;
    const int b = blockIdx.x / DIN;
    const int d = blockIdx.x % DIN;
    const float4* p0 = (const float4*)(g_y + ((size_t)(0 * BATCH + b) * DIN + d) * LSEQ);
    const float4* p1 = (const float4*)(g_y + ((size_t)(1 * BATCH + b) * DIN + d) * LSEQ);
    const float4* p2 = (const float4*)(g_y + ((size_t)(2 * BATCH + b) * DIN + d) * LSEQ);
    const float4* p3 = (const float4*)(g_y + ((size_t)(3 * BATCH + b) * DIN + d) * LSEQ);

    for (int t4 = tid; t4 < 1024; t4 += 256) {
        int i = t4 * 4;
        int w_ = i >> 6, h0 = i & 63;
        float4 v1 = p1[t4], v3 = p3[t4];
        s1[(h0 + 0) * 65 + w_] = v1.x; s1[(h0 + 1) * 65 + w_] = v1.y;
        s1[(h0 + 2) * 65 + w_] = v1.z; s1[(h0 + 3) * 65 + w_] = v1.w;
        s3[(h0 + 0) * 65 + w_] = v3.x; s3[(h0 + 1) * 65 + w_] = v3.y;
        s3[(h0 + 2) * 65 + w_] = v3.z; s3[(h0 + 3) * 65 + w_] = v3.w;
    }
    __syncthreads();

    float4* po = (float4*)(g_ysum + (size_t)(b * DIN + d) * LSEQ);
    for (int t4 = tid; t4 < 1024; t4 += 256) {
        int j = t4 * 4;
        int h = j >> 6, w0 = j & 63;
        float4 a = p0[t4], c = p2[t4];
        float4 r;
        r.x = a.x + c.x + s1[h * 65 + w0 + 0] + s3[h * 65 + w0 + 0];
        r.y = a.y + c.y + s1[h * 65 + w0 + 1] + s3[h * 65 + w0 + 1];
        r.z = a.z + c.z + s1[h * 65 + w0 + 2] + s3[h * 65 + w0 + 2];
        r.w = a.w + c.w + s1[h * 65 + w0 + 3] + s3[h * 65 + w0 + 3];
        po[t4] = r;
    }
}

// ================= K5: out-LN + gate + out_proj + residual =================
__global__ void k5_final(const float* __restrict__ onw, const float* __restrict__ onb,
                         const float* __restrict__ wout, float* __restrict__ out)
{
    extern __shared__ float sm[];
    float* yc = sm;                  // 192*36
    float* ws = sm + 192 * 36;       // 96*192
    const int tid = threadIdx.x, lane = tid & 31, warp = tid >> 5;
    const int b = blockIdx.x >> 7;
    const int l0 = (blockIdx.x & 127) << 5;

    for (int i = tid; i < 192 * 32; i += 256) {
        int d = i >> 5, p = i & 31;
        yc[d * 36 + p] = g_ysum[(size_t)(b * DIN + d) * LSEQ + l0 + p];
    }
    for (int i = tid; i < 96 * 192; i += 256) ws[i] = wout[i];
    __syncthreads();

    #pragma unroll
    for (int pp = 0; pp < 4; pp++) {
        const int p = warp * 4 + pp;
        float s = 0.f, s2 = 0.f, vv[6];
        #pragma unroll
        for (int j = 0; j < 6; j++) {
            float v = yc[(lane + 32 * j) * 36 + p];
            vv[j] = v; s += v; s2 += v * v;
        }
        #pragma unroll
        for (int o = 16; o > 0; o >>= 1) {
            s  += __shfl_xor_sync(0xffffffffu, s,  o);
            s2 += __shfl_xor_sync(0xffffffffu, s2, o);
        }
        float mu = s * (1.f / 192.f);
        float var = s2 * (1.f / 192.f) - mu * mu;
        float rstd = rsqrtf(var + 1e-5f);
        size_t zbase = ((size_t)(b * LSEQ + l0 + p)) * DIN;
        #pragma unroll
        for (int j = 0; j < 6; j++) {
            int dd = lane + 32 * j;
            float g = (vv[j] - mu) * rstd * onw[dd] + onb[dd];
            yc[dd * 36 + p] = g * g_zs[zbase + dd];
        }
    }
    __syncthreads();

    const int og = tid >> 3;
    const int pg = tid & 7;
    float acc[3][4];
    #pragma unroll
    for (int a = 0; a < 3; a++)
        #pragma unroll
        for (int c = 0; c < 4; c++) acc[a][c] = 0.f;

    #pragma unroll 4
    for (int dd = 0; dd < 192; dd++) {
        float4 gv = *(const float4*)&yc[dd * 36 + pg * 4];
        float g4[4] = {gv.x, gv.y, gv.z, gv.w};
        #pragma unroll
        for (int oi = 0; oi < 3; oi++) {
            float w2 = ws[(og * 3 + oi) * 192 + dd];
            #pragma unroll
            for (int pi = 0; pi < 4; pi++)
                acc[oi][pi] = fmaf(w2, g4[pi], acc[oi][pi]);
        }
    }
    __syncthreads();                 // all GEMM reads of yc done; reuse as staging

    float* buf = sm;                 // 32 x 100 staging (stride 100 words)
    #pragma unroll
    for (int oi = 0; oi < 3; oi++)
        #pragma unroll
        for (int pi = 0; pi < 4; pi++)
            buf[(pg * 4 + pi) * 100 + og * 3 + oi] = acc[oi][pi];
    __syncthreads();

    const float4* df4 = (const float4*)(g_diff + ((size_t)b * LSEQ + l0) * CDIM);
    float4* out4 = (float4*)(out + ((size_t)b * LSEQ + l0) * CDIM);
    for (int t = tid; t < 32 * 24; t += 256) {
        int p = t / 24, o4 = t % 24;
        float4 v = *(const float4*)&buf[p * 100 + o4 * 4];
        float4 dv = df4[p * 24 + o4];
        v.x += dv.x; v.y += dv.y; v.z += dv.z; v.w += dv.w;
        out4[p * 24 + o4] = v;
    }
}

// ================= launch =================
extern "C" void kernel_launch(void* const* d_in, const int* in_sizes, int n_in,
                              void* d_out, int out_size)
{
    const float* x     = (const float*)d_in[0];
    const float* y     = (const float*)d_in[1];
    const float* ln_w  = (const float*)d_in[2];
    const float* ln_b  = (const float*)d_in[3];
    const float* ipw   = (const float*)d_in[4];
    const float* cw    = (const float*)d_in[5];
    const float* cb    = (const float*)d_in[6];
    const float* xpw   = (const float*)d_in[7];
    const float* dtw   = (const float*)d_in[8];
    const float* dtb   = (const float*)d_in[9];
    const float* alog  = (const float*)d_in[10];
    const float* ds    = (const float*)d_in[11];
    const float* onw   = (const float*)d_in[12];
    const float* onb   = (const float*)d_in[13];
    const float* wout  = (const float*)d_in[14];
    float* out = (float*)d_out;

    const int smem1 = (96 * 64 + 96 * 128) * 4;
    const int smem3 = (192 * 64 + 192 * 48 + 38 * 65 + 192 * 6) * 4;
    const int smem5 = (192 * 36 + 96 * 192) * 4;
    cudaFuncSetAttribute(k1_prologue, cudaFuncAttributeMaxDynamicSharedMemorySize, smem1);
    cudaFuncSetAttribute(k3_xproj,   cudaFuncAttributeMaxDynamicSharedMemorySize, smem3);
    cudaFuncSetAttribute(k5_final,   cudaFuncAttributeMaxDynamicSharedMemorySize, smem5);

    k1_prologue<<<dim3(128, 3), 256, smem1>>>(x, y, ln_w, ln_b, ipw);
    k2_conv<<<(BATCH * DIN * LSEQ) / 256, 256>>>(cw, cb);
    k3_xproj<<<BATCH * 4 * (LSEQ / 64), 256, smem3>>>(xpw, dtw, dtb);
    k4a_scan<<<dim3(768, 2), 256>>>(alog);
    k4b_carry<<<NCH * NST / 256, 256>>>();
    k4c_scan<<<dim3(384, 2), 256>>>(alog, ds);
    k4t_merge<<<BATCH * DIN, 256>>>();
    k5_final<<<BATCH * (LSEQ / 32), 256, smem5>>>(onw, onb, wout, out);
}

// round 8
// speedup vs baseline: 3.3876x; 1.0523x over previous
#include <cuda_runtime.h>
#include <math.h>

#define BATCH 2
#define CDIM  96
#define DIN   192
#define NST   16
#define LSEQ  4096
#define NPIX  (BATCH*LSEQ)
#define NCH   (BATCH*4*DIN)     // 1536 scan channels
#define NCHUNK 16
#define CLEN  (LSEQ/NCHUNK)     // 256

// ---------------- persistent device scratch ----------------
__device__ float  g_diff [NPIX*CDIM];
__device__ float  g_zs   [NPIX*DIN];
__device__ float  g_xm   [BATCH*DIN*LSEQ];
__device__ float  g_x0   [BATCH*DIN*LSEQ];
__device__ float  g_x1   [BATCH*DIN*LSEQ];
__device__ float  g_delta[BATCH*4*DIN*LSEQ];
__device__ float4 g_bb4  [BATCH*4*(LSEQ/4)*16]; // B[n] grouped by 4 consecutive l
__device__ float4 g_bc4  [BATCH*4*LSEQ*8];      // (B_n, C_n, B_{n+8}, C_{n+8})
__device__ float  g_y    [4*BATCH*DIN*LSEQ];    // per-direction y, scan-native order
__device__ float  g_ysum [BATCH*DIN*LSEQ];      // merged y, canonical row-major
__device__ float  g_P    [NCH*NCHUNK*NST];
__device__ float  g_he   [NCH*NCHUNK*NST];
__device__ float  g_H    [NCH*NCHUNK*NST];

__device__ __forceinline__ float silu_f(float v){ return v / (1.f + __expf(-v)); }

// ================= K1: diff + LN + in_proj GEMM =================
__global__ void k1_prologue(const float* __restrict__ x, const float* __restrict__ y,
                            const float* __restrict__ lnw, const float* __restrict__ lnb,
                            const float* __restrict__ wproj)
{
    extern __shared__ float sm[];
    float* A_s = sm;            // 96*64
    float* W_s = sm + 96*64;    // 96*128
    const int tid = threadIdx.x, lane = tid & 31, warp = tid >> 5;
    const int pix0 = blockIdx.x * 64;
    const int oc = blockIdx.y;

    for (int pp = 0; pp < 8; pp++) {
        const int p = warp * 8 + pp;
        const int base = (pix0 + p) * CDIM;
        float vv[3]; float s = 0.f, s2 = 0.f;
        #pragma unroll
        for (int j = 0; j < 3; j++) {
            int ch = lane + 32 * j;
            float d = fabsf(x[base + ch] - y[base + ch]);
            if (oc == 0) g_diff[base + ch] = d;
            vv[j] = d; s += d; s2 += d * d;
        }
        #pragma unroll
        for (int o = 16; o > 0; o >>= 1) {
            s  += __shfl_xor_sync(0xffffffffu, s,  o);
            s2 += __shfl_xor_sync(0xffffffffu, s2, o);
        }
        float mu = s * (1.f / 96.f);
        float var = s2 * (1.f / 96.f) - mu * mu;
        float rstd = rsqrtf(var + 1e-5f);
        #pragma unroll
        for (int j = 0; j < 3; j++) {
            int ch = lane + 32 * j;
            A_s[ch * 64 + p] = (vv[j] - mu) * rstd * lnw[ch] + lnb[ch];
        }
    }
    for (int i = tid; i < 96 * 128; i += 256) {
        int kk = i % 96, j = i / 96;
        W_s[kk * 128 + j] = wproj[(oc * 128 + j) * 96 + kk];
    }
    __syncthreads();

    const int pg = tid & 7;
    const int og = tid >> 3;
    const float4* A4 = (const float4*)A_s;
    const float4* W4 = (const float4*)W_s;

    float acc[4][8];
    #pragma unroll
    for (int a = 0; a < 4; a++)
        #pragma unroll
        for (int b = 0; b < 8; b++) acc[a][b] = 0.f;

    #pragma unroll 4
    for (int kk = 0; kk < 96; kk++) {
        float4 a0 = A4[kk * 16 + pg * 2];
        float4 a1 = A4[kk * 16 + pg * 2 + 1];
        float4 w  = W4[kk * 32 + og];
        float ws4[4] = {w.x, w.y, w.z, w.w};
        float as8[8] = {a0.x, a0.y, a0.z, a0.w, a1.x, a1.y, a1.z, a1.w};
        #pragma unroll
        for (int jj = 0; jj < 4; jj++)
            #pragma unroll
            for (int pi = 0; pi < 8; pi++)
                acc[jj][pi] = fmaf(ws4[jj], as8[pi], acc[jj][pi]);
    }

    const int jg0 = oc * 128 + og * 4;
    const int pixb = pix0 + pg * 8;
    const int bb = pixb >> 12, lb = pixb & 4095;
    if (jg0 + 3 < DIN) {
        #pragma unroll
        for (int jj = 0; jj < 4; jj++) {
            float* row = g_xm + (size_t)(bb * DIN + jg0 + jj) * LSEQ + lb;
            *(float4*)row       = make_float4(acc[jj][0], acc[jj][1], acc[jj][2], acc[jj][3]);
            *(float4*)(row + 4) = make_float4(acc[jj][4], acc[jj][5], acc[jj][6], acc[jj][7]);
        }
    } else {
        const int zc = jg0 - DIN;
        #pragma unroll
        for (int pi = 0; pi < 8; pi++) {
            float* zp = g_zs + (size_t)(pixb + pi) * DIN + zc;
            *(float4*)zp = make_float4(silu_f(acc[0][pi]), silu_f(acc[1][pi]),
                                       silu_f(acc[2][pi]), silu_f(acc[3][pi]));
        }
    }
}

// ================= K2: depthwise conv + silu (smem-tiled, coalesced dual store) ==
__global__ void k2_conv(const float* __restrict__ cw, const float* __restrict__ cb)
{
    __shared__ float tin [64 * 65];
    __shared__ float tout[64 * 65];
    const int tid = threadIdx.x;
    const int bd = blockIdx.x;                 // b*DIN + d
    const int d = bd % DIN;
    const float* src = g_xm + (size_t)bd * LSEQ;

    for (int t = tid; t < 1024; t += 256) {
        float4 v = ((const float4*)src)[t];
        int i = t * 4;
        int h = i >> 6, w = i & 63;
        float* p = &tin[h * 65 + w];
        p[0] = v.x; p[1] = v.y; p[2] = v.z; p[3] = v.w;
    }
    float wreg[9];
    #pragma unroll
    for (int i = 0; i < 9; i++) wreg[i] = cw[d * 9 + i];
    const float bias = cb[d];
    __syncthreads();

    float* dst0 = g_x0 + (size_t)bd * LSEQ;
    for (int t = tid; t < 4096; t += 256) {
        int h = t >> 6, w = t & 63;
        float acc = bias;
        #pragma unroll
        for (int dy = 0; dy < 3; dy++) {
            int hh = h + dy - 1;
            if (hh < 0 || hh > 63) continue;
            #pragma unroll
            for (int dx = 0; dx < 3; dx++) {
                int ww = w + dx - 1;
                if (ww < 0 || ww > 63) continue;
                acc = fmaf(tin[hh * 65 + ww], wreg[dy * 3 + dx], acc);
            }
        }
        float v = silu_f(acc);
        dst0[t] = v;
        tout[h * 65 + w] = v;
    }
    __syncthreads();

    float* dst1 = g_x1 + (size_t)bd * LSEQ;
    for (int t = tid; t < 4096; t += 256) {
        int w = t >> 6, h = t & 63;
        dst1[t] = tout[h * 65 + w];
    }
}

// ================= K3: x_proj + dt_proj + softplus =================
__global__ void k3_xproj(const float* __restrict__ xpw, const float* __restrict__ dtw,
                         const float* __restrict__ dtb)
{
    extern __shared__ float sm[];
    float* u_s  = sm;                         // 192*64
    float* wp_t = u_s + 192 * 64;             // 192*48 (transposed, row-padded)
    float* xd_s = wp_t + 192 * 48;            // 38*65
    float* dw_s = xd_s + 38 * 65;             // 192*6
    float* db_s = dw_s + 192 * 6;             // 192
    const int tid = threadIdx.x;
    const int bk = blockIdx.x >> 6;
    const int b = bk >> 2, k = bk & 3;
    const int l0 = (blockIdx.x & 63) << 6;
    const float* seq = (k & 1) ? g_x1 : g_x0;

    for (int i = tid; i < 192 * 48; i += 256) wp_t[i] = 0.f;
    __syncthreads();

    for (int i = tid; i < 192 * 64; i += 256) {
        int d = i >> 6, c = i & 63;
        u_s[i] = seq[(size_t)(b * DIN + d) * LSEQ + l0 + c];
    }
    for (int i = tid; i < 38 * 192; i += 256) {
        int kk = i % 192, row = i / 192;
        wp_t[kk * 48 + row] = xpw[k * 38 * 192 + i];
    }
    for (int i = tid; i < 192 * 6;  i += 256) dw_s[i] = dtw[k * 192 * 6 + i];
    for (int i = tid; i < 192;      i += 256) db_s[i] = dtb[k * DIN + i];
    __syncthreads();

    const int col = tid & 63, grp = tid >> 6;
    float acc[12];
    #pragma unroll
    for (int j = 0; j < 12; j++) acc[j] = 0.f;
    const float4* wp4 = (const float4*)wp_t;
    #pragma unroll 2
    for (int kk = 0; kk < 192; kk++) {
        float uv = u_s[kk * 64 + col];
        float4 w0 = wp4[kk * 12 + grp * 3 + 0];
        float4 w1 = wp4[kk * 12 + grp * 3 + 1];
        float4 w2 = wp4[kk * 12 + grp * 3 + 2];
        acc[0]  = fmaf(w0.x, uv, acc[0]);  acc[1]  = fmaf(w0.y, uv, acc[1]);
        acc[2]  = fmaf(w0.z, uv, acc[2]);  acc[3]  = fmaf(w0.w, uv, acc[3]);
        acc[4]  = fmaf(w1.x, uv, acc[4]);  acc[5]  = fmaf(w1.y, uv, acc[5]);
        acc[6]  = fmaf(w1.z, uv, acc[6]);  acc[7]  = fmaf(w1.w, uv, acc[7]);
        acc[8]  = fmaf(w2.x, uv, acc[8]);  acc[9]  = fmaf(w2.y, uv, acc[9]);
        acc[10] = fmaf(w2.z, uv, acc[10]); acc[11] = fmaf(w2.w, uv, acc[11]);
    }
    #pragma unroll
    for (int j = 0; j < 12; j++) {
        int row = grp * 12 + j;
        if (row < 38) xd_s[row * 65 + col] = acc[j];
    }
    __syncthreads();

    // B-only layout for k4a
    const size_t lb4 = (size_t)bk * 1024 + (l0 >> 2);
    for (int i = tid; i < 16 * 64; i += 256) {
        int n = i & 15, cc = i >> 4;
        ((float*)g_bb4)[((lb4 + (cc >> 2)) * 16 + n) * 4 + (cc & 3)] = xd_s[(6 + n) * 65 + cc];
    }
    // interleaved (B,C) float4 layout for k4c
    const size_t bcbase = (size_t)bk * LSEQ + l0;
    for (int i = tid; i < 8 * 64; i += 256) {
        int n8 = i & 7, cc = i >> 3;
        float4 v;
        v.x = xd_s[(6  + n8) * 65 + cc];
        v.y = xd_s[(22 + n8) * 65 + cc];
        v.z = xd_s[(14 + n8) * 65 + cc];
        v.w = xd_s[(30 + n8) * 65 + cc];
        g_bc4[(bcbase + cc) * 8 + n8] = v;
    }
    // delta: hoist xd rows 0..5 (invariant over d) into registers
    float xdv[6];
    #pragma unroll
    for (int r = 0; r < 6; r++) xdv[r] = xd_s[r * 65 + col];
    const int dg = tid >> 6;
    const size_t dbase = (size_t)bk * DIN * LSEQ;
    for (int j = 0; j < 48; j++) {
        int d = dg + 4 * j;
        float val = db_s[d];
        #pragma unroll
        for (int r = 0; r < 6; r++)
            val = fmaf(dw_s[d * 6 + r], xdv[r], val);
        val = fmaxf(val, 0.f) + log1pf(__expf(-fabsf(val)));
        g_delta[dbase + (size_t)d * LSEQ + l0 + col] = val;
    }
}

// ================= K4a: local chunk scan =================
template<bool REV>
__device__ __forceinline__ void k4a_body(const int K0, const float* __restrict__ alog)
{
    const int lane = threadIdx.x & 31;
    const int w = blockIdx.x * 8 + (threadIdx.x >> 5);   // 0..6143
    const int chunk = w & (NCHUNK - 1);
    const int pair  = w >> 4;                            // 0..383
    const int half = lane >> 4, n = lane & 15;
    const int kk = pair / 192;
    const int rem = pair - kk * 192;
    const int b = rem / 96;
    const int d = (rem - b * 96) * 2 + half;
    const int k = K0 + kk;
    const int bk = b * 4 + k;
    const int ch = bk * DIN + d;
    const float An2 = -__expf(alog[(k * DIN + d) * NST + n]) * 1.44269504f;

    const float* dptr = g_delta + ((size_t)bk * DIN + d) * LSEQ;
    const float* uptr = (kk ? g_x1 : g_x0) + ((size_t)b * DIN + d) * LSEQ;
    const float4* bp4 = g_bb4 + (size_t)bk * 1024 * 16 + n;

    float h = 0.f, sdel = 0.f;
    if (!REV) {
        const int i0 = chunk * CLEN;
        const float4* dp4 = (const float4*)(dptr + i0);
        const float4* up4 = (const float4*)(uptr + i0);
        const float4* bb = bp4 + (size_t)(i0 >> 2) * 16;
        #pragma unroll 2
        for (int s = 0; s < CLEN / 4; s++) {
            float4 d4 = dp4[s]; float4 u4 = up4[s];
            float4 b4 = __ldg(bb + s * 16);
            float dd[4] = {d4.x, d4.y, d4.z, d4.w};
            float uu[4] = {u4.x, u4.y, u4.z, u4.w};
            float bv[4] = {b4.x, b4.y, b4.z, b4.w};
            sdel += (dd[0] + dd[1]) + (dd[2] + dd[3]);
            #pragma unroll
            for (int j = 0; j < 4; j++) {
                float a = exp2f(dd[j] * An2);
                h = fmaf(a, h, dd[j] * uu[j] * bv[j]);
            }
        }
    } else {
        const int ltop = LSEQ - chunk * CLEN;
        const float4* dp4 = (const float4*)(dptr + ltop) - 1;
        const float4* up4 = (const float4*)(uptr + ltop) - 1;
        const float4* bb = bp4 + (size_t)((ltop >> 2) - 1) * 16;
        #pragma unroll 2
        for (int s = 0; s < CLEN / 4; s++) {
            float4 d4 = dp4[-s]; float4 u4 = up4[-s];
            float4 b4 = __ldg(bb - s * 16);
            float dd[4] = {d4.x, d4.y, d4.z, d4.w};
            float uu[4] = {u4.x, u4.y, u4.z, u4.w};
            float bv[4] = {b4.x, b4.y, b4.z, b4.w};
            sdel += (dd[0] + dd[1]) + (dd[2] + dd[3]);
            #pragma unroll
            for (int j = 0; j < 4; j++) {
                const int e = 3 - j;
                float a = exp2f(dd[e] * An2);
                h = fmaf(a, h, dd[e] * uu[e] * bv[e]);
            }
        }
    }
    g_P [(ch * NCHUNK + chunk) * NST + n] = exp2f(An2 * sdel);
    g_he[(ch * NCHUNK + chunk) * NST + n] = h;
}

__global__ void __launch_bounds__(256, 6) k4a_scan(const float* __restrict__ alog)
{
    if (blockIdx.y == 0) k4a_body<false>(0, alog);
    else                 k4a_body<true >(2, alog);
}

// ================= K4b: carry across chunks =================
__global__ void k4b_carry()
{
    int idx = blockIdx.x * 256 + threadIdx.x;   // 0..24575
    int ch = idx >> 4, n = idx & 15;
    float H = 0.f;
    #pragma unroll
    for (int c = 0; c < NCHUNK; c++) {
        int o = (ch * NCHUNK + c) * NST + n;
        g_H[o] = H;
        H = fmaf(g_P[o], H, g_he[o]);
    }
}

// ================= K4c: seeded scan, emit y =================
template<bool REV>
__device__ __forceinline__ void k4c_body(const int K0, const float* __restrict__ alog,
                                         const float* __restrict__ ds)
{
    const int lane = threadIdx.x & 31;
    const int w = blockIdx.x * 8 + (threadIdx.x >> 5);   // 0..3071
    const int chunk = w & (NCHUNK - 1);
    const int quad  = w >> 4;                            // 0..191
    const int c2 = lane >> 3;
    const int n0 = lane & 7;
    const int kk = quad / 96;
    const int rem = quad - kk * 96;
    const int b = rem / 48;
    const int d = (rem - b * 48) * 4 + c2;
    const int k = K0 + kk;
    const int bk = b * 4 + k;
    const int ch = bk * DIN + d;

    const float An0 = -__expf(alog[(k * DIN + d) * NST + n0]) * 1.44269504f;
    const float An1 = -__expf(alog[(k * DIN + d) * NST + n0 + 8]) * 1.44269504f;
    const float Dd = ds[k * DIN + d];

    const float* dptr = g_delta + ((size_t)bk * DIN + d) * LSEQ;
    const float* uptr = (kk ? g_x1 : g_x0) + ((size_t)b * DIN + d) * LSEQ;
    const float4* bcp = g_bc4 + (size_t)bk * LSEQ * 8 + n0;
    float* yp = g_y + ((size_t)(k * BATCH + b) * DIN + d) * LSEQ;

    float h0 = g_H[(ch * NCHUNK + chunk) * NST + n0];
    float h1 = g_H[(ch * NCHUNK + chunk) * NST + n0 + 8];

    if (!REV) {
        const int i0 = chunk * CLEN;
        const float4* dp4 = (const float4*)(dptr + i0);
        const float4* up4 = (const float4*)(uptr + i0);
        const float4* bp = bcp + (size_t)i0 * 8;
        float4* yp4 = (float4*)(yp + i0);
        #pragma unroll 2
        for (int s = 0; s < CLEN / 4; s++) {
            float4 dv = dp4[s]; float4 uv = up4[s];
            float dd[4] = {dv.x, dv.y, dv.z, dv.w};
            float uu[4] = {uv.x, uv.y, uv.z, uv.w};
            float tr[4];
            #pragma unroll
            for (int j = 0; j < 4; j++) {
                float4 bc = __ldg(bp + (s * 4 + j) * 8);
                float du = dd[j] * uu[j];
                float a0 = exp2f(dd[j] * An0);
                float a1 = exp2f(dd[j] * An1);
                h0 = fmaf(a0, h0, du * bc.x);
                h1 = fmaf(a1, h1, du * bc.z);
                float t = fmaf(h1, bc.w, h0 * bc.y);
                t += __shfl_xor_sync(0xffffffffu, t, 4);
                t += __shfl_xor_sync(0xffffffffu, t, 2);
                t += __shfl_xor_sync(0xffffffffu, t, 1);
                tr[j] = fmaf(Dd, uu[j], t);
            }
            if (n0 == 0) yp4[s] = make_float4(tr[0], tr[1], tr[2], tr[3]);
        }
    } else {
        const int ltop = LSEQ - chunk * CLEN;
        const float4* dp4 = (const float4*)(dptr + ltop) - 1;
        const float4* up4 = (const float4*)(uptr + ltop) - 1;
        const float4* bp = bcp + (size_t)(ltop - 1) * 8;
        float4* yp4 = (float4*)(yp + ltop) - 1;
        #pragma unroll 2
        for (int s = 0; s < CLEN / 4; s++) {
            float4 dv = dp4[-s]; float4 uv = up4[-s];
            float dd[4] = {dv.x, dv.y, dv.z, dv.w};
            float uu[4] = {uv.x, uv.y, uv.z, uv.w};
            float tr[4];
            #pragma unroll
            for (int j = 0; j < 4; j++) {
                const int e = 3 - j;
                float4 bc = __ldg(bp - (s * 4 + j) * 8);
                float du = dd[e] * uu[e];
                float a0 = exp2f(dd[e] * An0);
                float a1 = exp2f(dd[e] * An1);
                h0 = fmaf(a0, h0, du * bc.x);
                h1 = fmaf(a1, h1, du * bc.z);
                float t = fmaf(h1, bc.w, h0 * bc.y);
                t += __shfl_xor_sync(0xffffffffu, t, 4);
                t += __shfl_xor_sync(0xffffffffu, t, 2);
                t += __shfl_xor_sync(0xffffffffu, t, 1);
                tr[e] = fmaf(Dd, uu[e], t);
            }
            if (n0 == 0) yp4[-s] = make_float4(tr[0], tr[1], tr[2], tr[3]);
        }
    }
}

__global__ void __launch_bounds__(256, 6) k4c_scan(const float* __restrict__ alog,
                                                   const float* __restrict__ ds)
{
    if (blockIdx.y == 0) k4c_body<false>(0, alog, ds);
    else                 k4c_body<true >(2, alog, ds);
}

// ================= K4t: transpose wh planes + merge all 4 into g_ysum =========
__global__ void k4t_merge()
{
    __shared__ float s1[64 * 65];
    __shared__ float s3[64 * 65];
    const int tid = threadIdx.x;
    const int b = blockIdx.x / DIN;
    const int d = blockIdx.x % DIN;
    const float4* p0 = (const float4*)(g_y + ((size_t)(0 * BATCH + b) * DIN + d) * LSEQ);
    const float4* p1 = (const float4*)(g_y + ((size_t)(1 * BATCH + b) * DIN + d) * LSEQ);
    const float4* p2 = (const float4*)(g_y + ((size_t)(2 * BATCH + b) * DIN + d) * LSEQ);
    const float4* p3 = (const float4*)(g_y + ((size_t)(3 * BATCH + b) * DIN + d) * LSEQ);

    for (int t4 = tid; t4 < 1024; t4 += 256) {
        int i = t4 * 4;
        int w_ = i >> 6, h0 = i & 63;
        float4 v1 = p1[t4], v3 = p3[t4];
        s1[(h0 + 0) * 65 + w_] = v1.x; s1[(h0 + 1) * 65 + w_] = v1.y;
        s1[(h0 + 2) * 65 + w_] = v1.z; s1[(h0 + 3) * 65 + w_] = v1.w;
        s3[(h0 + 0) * 65 + w_] = v3.x; s3[(h0 + 1) * 65 + w_] = v3.y;
        s3[(h0 + 2) * 65 + w_] = v3.z; s3[(h0 + 3) * 65 + w_] = v3.w;
    }
    __syncthreads();

    float4* po = (float4*)(g_ysum + (size_t)(b * DIN + d) * LSEQ);
    for (int t4 = tid; t4 < 1024; t4 += 256) {
        int j = t4 * 4;
        int h = j >> 6, w0 = j & 63;
        float4 a = p0[t4], c = p2[t4];
        float4 r;
        r.x = a.x + c.x + s1[h * 65 + w0 + 0] + s3[h * 65 + w0 + 0];
        r.y = a.y + c.y + s1[h * 65 + w0 + 1] + s3[h * 65 + w0 + 1];
        r.z = a.z + c.z + s1[h * 65 + w0 + 2] + s3[h * 65 + w0 + 2];
        r.w = a.w + c.w + s1[h * 65 + w0 + 3] + s3[h * 65 + w0 + 3];
        po[t4] = r;
    }
}

// ================= K5: out-LN + gate + out_proj + residual =================
__global__ void k5_final(const float* __restrict__ onw, const float* __restrict__ onb,
                         const float* __restrict__ wout, float* __restrict__ out)
{
    extern __shared__ float sm[];
    float* yc = sm;                  // 192*36
    float* ws = sm + 192 * 36;       // 96*192
    const int tid = threadIdx.x, lane = tid & 31, warp = tid >> 5;
    const int b = blockIdx.x >> 7;
    const int l0 = (blockIdx.x & 127) << 5;

    for (int i = tid; i < 192 * 32; i += 256) {
        int d = i >> 5, p = i & 31;
        yc[d * 36 + p] = g_ysum[(size_t)(b * DIN + d) * LSEQ + l0 + p];
    }
    for (int i = tid; i < 96 * 192; i += 256) ws[i] = wout[i];
    __syncthreads();

    #pragma unroll
    for (int pp = 0; pp < 4; pp++) {
        const int p = warp * 4 + pp;
        float s = 0.f, s2 = 0.f, vv[6];
        #pragma unroll
        for (int j = 0; j < 6; j++) {
            float v = yc[(lane + 32 * j) * 36 + p];
            vv[j] = v; s += v; s2 += v * v;
        }
        #pragma unroll
        for (int o = 16; o > 0; o >>= 1) {
            s  += __shfl_xor_sync(0xffffffffu, s,  o);
            s2 += __shfl_xor_sync(0xffffffffu, s2, o);
        }
        float mu = s * (1.f / 192.f);
        float var = s2 * (1.f / 192.f) - mu * mu;
        float rstd = rsqrtf(var + 1e-5f);
        size_t zbase = ((size_t)(b * LSEQ + l0 + p)) * DIN;
        #pragma unroll
        for (int j = 0; j < 6; j++) {
            int dd = lane + 32 * j;
            float g = (vv[j] - mu) * rstd * onw[dd] + onb[dd];
            yc[dd * 36 + p] = g * g_zs[zbase + dd];
        }
    }
    __syncthreads();

    const int og = tid >> 3;
    const int pg = tid & 7;
    float acc[3][4];
    #pragma unroll
    for (int a = 0; a < 3; a++)
        #pragma unroll
        for (int c = 0; c < 4; c++) acc[a][c] = 0.f;

    #pragma unroll 4
    for (int dd = 0; dd < 192; dd++) {
        float4 gv = *(const float4*)&yc[dd * 36 + pg * 4];
        float g4[4] = {gv.x, gv.y, gv.z, gv.w};
        #pragma unroll
        for (int oi = 0; oi < 3; oi++) {
            float w2 = ws[(og * 3 + oi) * 192 + dd];
            #pragma unroll
            for (int pi = 0; pi < 4; pi++)
                acc[oi][pi] = fmaf(w2, g4[pi], acc[oi][pi]);
        }
    }
    __syncthreads();

    float* buf = sm;                 // 32 x 100 staging
    #pragma unroll
    for (int oi = 0; oi < 3; oi++)
        #pragma unroll
        for (int pi = 0; pi < 4; pi++)
            buf[(pg * 4 + pi) * 100 + og * 3 + oi] = acc[oi][pi];
    __syncthreads();

    const float4* df4 = (const float4*)(g_diff + ((size_t)b * LSEQ + l0) * CDIM);
    float4* out4 = (float4*)(out + ((size_t)b * LSEQ + l0) * CDIM);
    for (int t = tid; t < 32 * 24; t += 256) {
        int p = t / 24, o4 = t % 24;
        float4 v = *(const float4*)&buf[p * 100 + o4 * 4];
        float4 dv = df4[p * 24 + o4];
        v.x += dv.x; v.y += dv.y; v.z += dv.z; v.w += dv.w;
        out4[p * 24 + o4] = v;
    }
}

// ================= launch =================
extern "C" void kernel_launch(void* const* d_in, const int* in_sizes, int n_in,
                              void* d_out, int out_size)
{
    const float* x     = (const float*)d_in[0];
    const float* y     = (const float*)d_in[1];
    const float* ln_w  = (const float*)d_in[2];
    const float* ln_b  = (const float*)d_in[3];
    const float* ipw   = (const float*)d_in[4];
    const float* cw    = (const float*)d_in[5];
    const float* cb    = (const float*)d_in[6];
    const float* xpw   = (const float*)d_in[7];
    const float* dtw   = (const float*)d_in[8];
    const float* dtb   = (const float*)d_in[9];
    const float* alog  = (const float*)d_in[10];
    const float* ds    = (const float*)d_in[11];
    const float* onw   = (const float*)d_in[12];
    const float* onb   = (const float*)d_in[13];
    const float* wout  = (const float*)d_in[14];
    float* out = (float*)d_out;

    const int smem1 = (96 * 64 + 96 * 128) * 4;
    const int smem3 = (192 * 64 + 192 * 48 + 38 * 65 + 192 * 6 + 192) * 4;
    const int smem5 = (192 * 36 + 96 * 192) * 4;
    cudaFuncSetAttribute(k1_prologue, cudaFuncAttributeMaxDynamicSharedMemorySize, smem1);
    cudaFuncSetAttribute(k3_xproj,   cudaFuncAttributeMaxDynamicSharedMemorySize, smem3);
    cudaFuncSetAttribute(k5_final,   cudaFuncAttributeMaxDynamicSharedMemorySize, smem5);

    k1_prologue<<<dim3(128, 3), 256, smem1>>>(x, y, ln_w, ln_b, ipw);
    k2_conv<<<BATCH * DIN, 256>>>(cw, cb);
    k3_xproj<<<BATCH * 4 * (LSEQ / 64), 256, smem3>>>(xpw, dtw, dtb);
    k4a_scan<<<dim3(768, 2), 256>>>(alog);
    k4b_carry<<<NCH * NST / 256, 256>>>();
    k4c_scan<<<dim3(384, 2), 256>>>(alog, ds);
    k4t_merge<<<BATCH * DIN, 256>>>();
    k5_final<<<BATCH * (LSEQ / 32), 256, smem5>>>(onw, onb, wout, out);
}

// round 9
// speedup vs baseline: 3.5126x; 1.0369x over previous
#include <cuda_runtime.h>
#include <math.h>

#define BATCH 2
#define CDIM  96
#define DIN   192
#define NST   16
#define LSEQ  4096
#define NPIX  (BATCH*LSEQ)
#define NCH   (BATCH*4*DIN)     // 1536 scan channels
#define NCHUNK 16
#define CLEN  (LSEQ/NCHUNK)     // 256

// ---------------- persistent device scratch ----------------
__device__ float  g_diff [NPIX*CDIM];
__device__ float  g_zs   [NPIX*DIN];
__device__ float  g_xm   [BATCH*DIN*LSEQ];
__device__ float  g_x0   [BATCH*DIN*LSEQ];
__device__ float  g_x1   [BATCH*DIN*LSEQ];
__device__ float  g_delta[BATCH*4*DIN*LSEQ];
__device__ float4 g_bb4  [BATCH*4*(LSEQ/4)*16]; // B[n] grouped by 4 consecutive l
__device__ float4 g_bc4  [BATCH*4*LSEQ*8];      // (B_n, C_n, B_{n+8}, C_{n+8})
__device__ float  g_y    [4*BATCH*DIN*LSEQ];    // per-direction y, scan-native order
__device__ float  g_ysum [BATCH*DIN*LSEQ];      // merged y, canonical row-major
__device__ float  g_P    [NCH*NCHUNK*NST];
__device__ float  g_he   [NCH*NCHUNK*NST];
__device__ float  g_H    [NCH*NCHUNK*NST];

__device__ __forceinline__ float silu_f(float v){ return v / (1.f + __expf(-v)); }

// ================= K1: diff + LN + in_proj GEMM =================
__global__ void k1_prologue(const float* __restrict__ x, const float* __restrict__ y,
                            const float* __restrict__ lnw, const float* __restrict__ lnb,
                            const float* __restrict__ wproj)
{
    extern __shared__ float sm[];
    float* A_s = sm;            // 96*64
    float* W_s = sm + 96*64;    // 96*128
    const int tid = threadIdx.x, lane = tid & 31, warp = tid >> 5;
    const int pix0 = blockIdx.x * 64;
    const int oc = blockIdx.y;

    for (int pp = 0; pp < 8; pp++) {
        const int p = warp * 8 + pp;
        const int base = (pix0 + p) * CDIM;
        float vv[3]; float s = 0.f, s2 = 0.f;
        #pragma unroll
        for (int j = 0; j < 3; j++) {
            int ch = lane + 32 * j;
            float d = fabsf(x[base + ch] - y[base + ch]);
            if (oc == 0) g_diff[base + ch] = d;
            vv[j] = d; s += d; s2 += d * d;
        }
        #pragma unroll
        for (int o = 16; o > 0; o >>= 1) {
            s  += __shfl_xor_sync(0xffffffffu, s,  o);
            s2 += __shfl_xor_sync(0xffffffffu, s2, o);
        }
        float mu = s * (1.f / 96.f);
        float var = s2 * (1.f / 96.f) - mu * mu;
        float rstd = rsqrtf(var + 1e-5f);
        #pragma unroll
        for (int j = 0; j < 3; j++) {
            int ch = lane + 32 * j;
            A_s[ch * 64 + p] = (vv[j] - mu) * rstd * lnw[ch] + lnb[ch];
        }
    }
    for (int i = tid; i < 96 * 128; i += 256) {
        int kk = i % 96, j = i / 96;
        W_s[kk * 128 + j] = wproj[(oc * 128 + j) * 96 + kk];
    }
    __syncthreads();

    const int pg = tid & 7;
    const int og = tid >> 3;
    const float4* A4 = (const float4*)A_s;
    const float4* W4 = (const float4*)W_s;

    float acc[4][8];
    #pragma unroll
    for (int a = 0; a < 4; a++)
        #pragma unroll
        for (int b = 0; b < 8; b++) acc[a][b] = 0.f;

    #pragma unroll 4
    for (int kk = 0; kk < 96; kk++) {
        float4 a0 = A4[kk * 16 + pg * 2];
        float4 a1 = A4[kk * 16 + pg * 2 + 1];
        float4 w  = W4[kk * 32 + og];
        float ws4[4] = {w.x, w.y, w.z, w.w};
        float as8[8] = {a0.x, a0.y, a0.z, a0.w, a1.x, a1.y, a1.z, a1.w};
        #pragma unroll
        for (int jj = 0; jj < 4; jj++)
            #pragma unroll
            for (int pi = 0; pi < 8; pi++)
                acc[jj][pi] = fmaf(ws4[jj], as8[pi], acc[jj][pi]);
    }

    const int jg0 = oc * 128 + og * 4;
    const int pixb = pix0 + pg * 8;
    const int bb = pixb >> 12, lb = pixb & 4095;
    if (jg0 + 3 < DIN) {
        #pragma unroll
        for (int jj = 0; jj < 4; jj++) {
            float* row = g_xm + (size_t)(bb * DIN + jg0 + jj) * LSEQ + lb;
            *(float4*)row       = make_float4(acc[jj][0], acc[jj][1], acc[jj][2], acc[jj][3]);
            *(float4*)(row + 4) = make_float4(acc[jj][4], acc[jj][5], acc[jj][6], acc[jj][7]);
        }
    } else {
        const int zc = jg0 - DIN;
        #pragma unroll
        for (int pi = 0; pi < 8; pi++) {
            float* zp = g_zs + (size_t)(pixb + pi) * DIN + zc;
            *(float4*)zp = make_float4(silu_f(acc[0][pi]), silu_f(acc[1][pi]),
                                       silu_f(acc[2][pi]), silu_f(acc[3][pi]));
        }
    }
}

// ================= K2: depthwise conv + silu (smem-tiled, coalesced dual store) ==
__global__ void k2_conv(const float* __restrict__ cw, const float* __restrict__ cb)
{
    __shared__ float tin [64 * 65];
    __shared__ float tout[64 * 65];
    const int tid = threadIdx.x;
    const int bd = blockIdx.x;                 // b*DIN + d
    const int d = bd % DIN;
    const float* src = g_xm + (size_t)bd * LSEQ;

    for (int t = tid; t < 1024; t += 256) {
        float4 v = ((const float4*)src)[t];
        int i = t * 4;
        int h = i >> 6, w = i & 63;
        float* p = &tin[h * 65 + w];
        p[0] = v.x; p[1] = v.y; p[2] = v.z; p[3] = v.w;
    }
    float wreg[9];
    #pragma unroll
    for (int i = 0; i < 9; i++) wreg[i] = cw[d * 9 + i];
    const float bias = cb[d];
    __syncthreads();

    float* dst0 = g_x0 + (size_t)bd * LSEQ;
    for (int t = tid; t < 4096; t += 256) {
        int h = t >> 6, w = t & 63;
        float acc = bias;
        #pragma unroll
        for (int dy = 0; dy < 3; dy++) {
            int hh = h + dy - 1;
            if (hh < 0 || hh > 63) continue;
            #pragma unroll
            for (int dx = 0; dx < 3; dx++) {
                int ww = w + dx - 1;
                if (ww < 0 || ww > 63) continue;
                acc = fmaf(tin[hh * 65 + ww], wreg[dy * 3 + dx], acc);
            }
        }
        float v = silu_f(acc);
        dst0[t] = v;
        tout[h * 65 + w] = v;
    }
    __syncthreads();

    float* dst1 = g_x1 + (size_t)bd * LSEQ;
    for (int t = tid; t < 4096; t += 256) {
        int w = t >> 6, h = t & 63;
        dst1[t] = tout[h * 65 + w];
    }
}

// ================= K3: x_proj + dt_proj + softplus =================
__global__ void k3_xproj(const float* __restrict__ xpw, const float* __restrict__ dtw,
                         const float* __restrict__ dtb)
{
    extern __shared__ float sm[];
    float* u_s  = sm;                         // 192*64
    float* wp_t = u_s + 192 * 64;             // 192*48
    float* xd_s = wp_t + 192 * 48;            // 38*65
    float* dw_s = xd_s + 38 * 65;             // 192*6
    float* db_s = dw_s + 192 * 6;             // 192
    const int tid = threadIdx.x;
    const int bk = blockIdx.x >> 6;
    const int b = bk >> 2, k = bk & 3;
    const int l0 = (blockIdx.x & 63) << 6;
    const float* seq = (k & 1) ? g_x1 : g_x0;

    for (int i = tid; i < 192 * 48; i += 256) wp_t[i] = 0.f;
    __syncthreads();

    for (int i = tid; i < 192 * 64; i += 256) {
        int d = i >> 6, c = i & 63;
        u_s[i] = seq[(size_t)(b * DIN + d) * LSEQ + l0 + c];
    }
    for (int i = tid; i < 38 * 192; i += 256) {
        int kk = i % 192, row = i / 192;
        wp_t[kk * 48 + row] = xpw[k * 38 * 192 + i];
    }
    for (int i = tid; i < 192 * 6;  i += 256) dw_s[i] = dtw[k * 192 * 6 + i];
    for (int i = tid; i < 192;      i += 256) db_s[i] = dtb[k * DIN + i];
    __syncthreads();

    const int col = tid & 63, grp = tid >> 6;
    float acc[12];
    #pragma unroll
    for (int j = 0; j < 12; j++) acc[j] = 0.f;
    const float4* wp4 = (const float4*)wp_t;
    #pragma unroll 2
    for (int kk = 0; kk < 192; kk++) {
        float uv = u_s[kk * 64 + col];
        float4 w0 = wp4[kk * 12 + grp * 3 + 0];
        float4 w1 = wp4[kk * 12 + grp * 3 + 1];
        float4 w2 = wp4[kk * 12 + grp * 3 + 2];
        acc[0]  = fmaf(w0.x, uv, acc[0]);  acc[1]  = fmaf(w0.y, uv, acc[1]);
        acc[2]  = fmaf(w0.z, uv, acc[2]);  acc[3]  = fmaf(w0.w, uv, acc[3]);
        acc[4]  = fmaf(w1.x, uv, acc[4]);  acc[5]  = fmaf(w1.y, uv, acc[5]);
        acc[6]  = fmaf(w1.z, uv, acc[6]);  acc[7]  = fmaf(w1.w, uv, acc[7]);
        acc[8]  = fmaf(w2.x, uv, acc[8]);  acc[9]  = fmaf(w2.y, uv, acc[9]);
        acc[10] = fmaf(w2.z, uv, acc[10]); acc[11] = fmaf(w2.w, uv, acc[11]);
    }
    #pragma unroll
    for (int j = 0; j < 12; j++) {
        int row = grp * 12 + j;
        if (row < 38) xd_s[row * 65 + col] = acc[j];
    }
    __syncthreads();

    const size_t lb4 = (size_t)bk * 1024 + (l0 >> 2);
    for (int i = tid; i < 16 * 64; i += 256) {
        int n = i & 15, cc = i >> 4;
        ((float*)g_bb4)[((lb4 + (cc >> 2)) * 16 + n) * 4 + (cc & 3)] = xd_s[(6 + n) * 65 + cc];
    }
    const size_t bcbase = (size_t)bk * LSEQ + l0;
    for (int i = tid; i < 8 * 64; i += 256) {
        int n8 = i & 7, cc = i >> 3;
        float4 v;
        v.x = xd_s[(6  + n8) * 65 + cc];
        v.y = xd_s[(22 + n8) * 65 + cc];
        v.z = xd_s[(14 + n8) * 65 + cc];
        v.w = xd_s[(30 + n8) * 65 + cc];
        g_bc4[(bcbase + cc) * 8 + n8] = v;
    }
    float xdv[6];
    #pragma unroll
    for (int r = 0; r < 6; r++) xdv[r] = xd_s[r * 65 + col];
    const int dg = tid >> 6;
    const size_t dbase = (size_t)bk * DIN * LSEQ;
    for (int j = 0; j < 48; j++) {
        int d = dg + 4 * j;
        float val = db_s[d];
        #pragma unroll
        for (int r = 0; r < 6; r++)
            val = fmaf(dw_s[d * 6 + r], xdv[r], val);
        val = fmaxf(val, 0.f) + log1pf(__expf(-fabsf(val)));
        g_delta[dbase + (size_t)d * LSEQ + l0 + col] = val;
    }
}

// ================= K4a: local chunk scan (smem-staged B) =================
// block = 8 pairs of the SAME (b,kk,chunk); grid ((2*2*16)*12, 2)
template<bool REV>
__device__ __forceinline__ void k4a_body(const int K0, const float* __restrict__ alog)
{
    __shared__ float4 sB[1024];    // 64 lblk x 16 n = 16KB
    const int tid = threadIdx.x;
    const int lane = tid & 31, wi = tid >> 5;
    int bx = blockIdx.x;
    const int pb = bx % 12; bx /= 12;
    const int chunk = bx & 15; bx >>= 4;
    const int kk = bx & 1;
    const int b  = bx >> 1;
    const int p = pb * 8 + wi;                 // 0..95
    const int half = lane >> 4, n = lane & 15;
    const int d = p * 2 + half;                // 0..191
    const int k = K0 + kk;
    const int bk = b * 4 + k;
    const int ch = bk * DIN + d;
    const float An2 = -__expf(alog[(k * DIN + d) * NST + n]) * 1.44269504f;

    // stage B tile for this (bk, chunk)
    {
        const float4* src = g_bb4 + ((size_t)bk * 1024 + chunk * 64) * 16;
        #pragma unroll
        for (int i = 0; i < 4; i++) sB[tid + i * 256] = src[tid + i * 256];
    }
    __syncthreads();

    const float* dptr = g_delta + ((size_t)bk * DIN + d) * LSEQ;
    const float* uptr = (kk ? g_x1 : g_x0) + ((size_t)b * DIN + d) * LSEQ;

    float h = 0.f, sdel = 0.f;
    if (!REV) {
        const int i0 = chunk * CLEN;
        const float4* dp4 = (const float4*)(dptr + i0);
        const float4* up4 = (const float4*)(uptr + i0);
        #pragma unroll 2
        for (int s = 0; s < CLEN / 4; s++) {
            float4 d4 = dp4[s]; float4 u4 = up4[s];
            float4 b4 = sB[s * 16 + n];
            float dd[4] = {d4.x, d4.y, d4.z, d4.w};
            float uu[4] = {u4.x, u4.y, u4.z, u4.w};
            float bv[4] = {b4.x, b4.y, b4.z, b4.w};
            sdel += (dd[0] + dd[1]) + (dd[2] + dd[3]);
            #pragma unroll
            for (int j = 0; j < 4; j++) {
                float a = exp2f(dd[j] * An2);
                h = fmaf(a, h, dd[j] * uu[j] * bv[j]);
            }
        }
    } else {
        const int ltop = LSEQ - chunk * CLEN;
        const float4* dp4 = (const float4*)(dptr + ltop) - 1;
        const float4* up4 = (const float4*)(uptr + ltop) - 1;
        #pragma unroll 2
        for (int s = 0; s < CLEN / 4; s++) {
            float4 d4 = dp4[-s]; float4 u4 = up4[-s];
            float4 b4 = sB[(63 - s) * 16 + n];
            float dd[4] = {d4.x, d4.y, d4.z, d4.w};
            float uu[4] = {u4.x, u4.y, u4.z, u4.w};
            float bv[4] = {b4.x, b4.y, b4.z, b4.w};
            sdel += (dd[0] + dd[1]) + (dd[2] + dd[3]);
            #pragma unroll
            for (int j = 0; j < 4; j++) {
                const int e = 3 - j;
                float a = exp2f(dd[e] * An2);
                h = fmaf(a, h, dd[e] * uu[e] * bv[e]);
            }
        }
    }
    g_P [(ch * NCHUNK + chunk) * NST + n] = exp2f(An2 * sdel);
    g_he[(ch * NCHUNK + chunk) * NST + n] = h;
}

__global__ void __launch_bounds__(256, 6) k4a_scan(const float* __restrict__ alog)
{
    if (blockIdx.y == 0) k4a_body<false>(0, alog);
    else                 k4a_body<true >(2, alog);
}

// ================= K4b: carry across chunks =================
__global__ void k4b_carry()
{
    int idx = blockIdx.x * 256 + threadIdx.x;   // 0..24575
    int ch = idx >> 4, n = idx & 15;
    float H = 0.f;
    #pragma unroll
    for (int c = 0; c < NCHUNK; c++) {
        int o = (ch * NCHUNK + c) * NST + n;
        g_H[o] = H;
        H = fmaf(g_P[o], H, g_he[o]);
    }
}

// ================= K4c: seeded scan, emit y (smem-staged BC) =================
// block = 8 quads of the SAME (b,kk,chunk); grid ((2*2*16)*6, 2)
template<bool REV>
__device__ __forceinline__ void k4c_body(const int K0, const float* __restrict__ alog,
                                         const float* __restrict__ ds)
{
    __shared__ float4 sBC[2048];   // 256 l x 8 n = 32KB
    const int tid = threadIdx.x;
    const int lane = tid & 31, wi = tid >> 5;
    int bx = blockIdx.x;
    const int qb = bx % 6; bx /= 6;
    const int chunk = bx & 15; bx >>= 4;
    const int kk = bx & 1;
    const int b  = bx >> 1;
    const int q = qb * 8 + wi;                 // 0..47
    const int c2 = lane >> 3;
    const int n0 = lane & 7;
    const int d = q * 4 + c2;                  // 0..191
    const int k = K0 + kk;
    const int bk = b * 4 + k;
    const int ch = bk * DIN + d;

    // stage BC tile for this (bk, chunk)
    {
        const float4* src = g_bc4 + ((size_t)bk * LSEQ + chunk * CLEN) * 8;
        #pragma unroll
        for (int i = 0; i < 8; i++) sBC[tid + i * 256] = src[tid + i * 256];
    }
    __syncthreads();

    const float An0 = -__expf(alog[(k * DIN + d) * NST + n0]) * 1.44269504f;
    const float An1 = -__expf(alog[(k * DIN + d) * NST + n0 + 8]) * 1.44269504f;
    const float Dd = ds[k * DIN + d];

    const float* dptr = g_delta + ((size_t)bk * DIN + d) * LSEQ;
    const float* uptr = (kk ? g_x1 : g_x0) + ((size_t)b * DIN + d) * LSEQ;
    float* yp = g_y + ((size_t)(k * BATCH + b) * DIN + d) * LSEQ;

    float h0 = g_H[(ch * NCHUNK + chunk) * NST + n0];
    float h1 = g_H[(ch * NCHUNK + chunk) * NST + n0 + 8];

    if (!REV) {
        const int i0 = chunk * CLEN;
        const float4* dp4 = (const float4*)(dptr + i0);
        const float4* up4 = (const float4*)(uptr + i0);
        float4* yp4 = (float4*)(yp + i0);
        #pragma unroll 2
        for (int s = 0; s < CLEN / 4; s++) {
            float4 dv = dp4[s]; float4 uv = up4[s];
            float dd[4] = {dv.x, dv.y, dv.z, dv.w};
            float uu[4] = {uv.x, uv.y, uv.z, uv.w};
            float tr[4];
            #pragma unroll
            for (int j = 0; j < 4; j++) {
                float4 bc = sBC[(s * 4 + j) * 8 + n0];
                float du = dd[j] * uu[j];
                float a0 = exp2f(dd[j] * An0);
                float a1 = exp2f(dd[j] * An1);
                h0 = fmaf(a0, h0, du * bc.x);
                h1 = fmaf(a1, h1, du * bc.z);
                float t = fmaf(h1, bc.w, h0 * bc.y);
                t += __shfl_xor_sync(0xffffffffu, t, 4);
                t += __shfl_xor_sync(0xffffffffu, t, 2);
                t += __shfl_xor_sync(0xffffffffu, t, 1);
                tr[j] = fmaf(Dd, uu[j], t);
            }
            if (n0 == 0) yp4[s] = make_float4(tr[0], tr[1], tr[2], tr[3]);
        }
    } else {
        const int ltop = LSEQ - chunk * CLEN;
        const float4* dp4 = (const float4*)(dptr + ltop) - 1;
        const float4* up4 = (const float4*)(uptr + ltop) - 1;
        float4* yp4 = (float4*)(yp + ltop) - 1;
        #pragma unroll 2
        for (int s = 0; s < CLEN / 4; s++) {
            float4 dv = dp4[-s]; float4 uv = up4[-s];
            float dd[4] = {dv.x, dv.y, dv.z, dv.w};
            float uu[4] = {uv.x, uv.y, uv.z, uv.w};
            float tr[4];
            #pragma unroll
            for (int j = 0; j < 4; j++) {
                const int e = 3 - j;
                float4 bc = sBC[(CLEN - 1 - (s * 4 + j)) * 8 + n0];
                float du = dd[e] * uu[e];
                float a0 = exp2f(dd[e] * An0);
                float a1 = exp2f(dd[e] * An1);
                h0 = fmaf(a0, h0, du * bc.x);
                h1 = fmaf(a1, h1, du * bc.z);
                float t = fmaf(h1, bc.w, h0 * bc.y);
                t += __shfl_xor_sync(0xffffffffu, t, 4);
                t += __shfl_xor_sync(0xffffffffu, t, 2);
                t += __shfl_xor_sync(0xffffffffu, t, 1);
                tr[e] = fmaf(Dd, uu[e], t);
            }
            if (n0 == 0) yp4[-s] = make_float4(tr[0], tr[1], tr[2], tr[3]);
        }
    }
}

__global__ void __launch_bounds__(256, 6) k4c_scan(const float* __restrict__ alog,
                                                   const float* __restrict__ ds)
{
    if (blockIdx.y == 0) k4c_body<false>(0, alog, ds);
    else                 k4c_body<true >(2, alog, ds);
}

// ================= K4t: transpose wh planes + merge all 4 into g_ysum =========
__global__ void k4t_merge()
{
    __shared__ float s1[64 * 65];
    __shared__ float s3[64 * 65];
    const int tid = threadIdx.x;
    const int b = blockIdx.x / DIN;
    const int d = blockIdx.x % DIN;
    const float4* p0 = (const float4*)(g_y + ((size_t)(0 * BATCH + b) * DIN + d) * LSEQ);
    const float4* p1 = (const float4*)(g_y + ((size_t)(1 * BATCH + b) * DIN + d) * LSEQ);
    const float4* p2 = (const float4*)(g_y + ((size_t)(2 * BATCH + b) * DIN + d) * LSEQ);
    const float4* p3 = (const float4*)(g_y + ((size_t)(3 * BATCH + b) * DIN + d) * LSEQ);

    for (int t4 = tid; t4 < 1024; t4 += 256) {
        int i = t4 * 4;
        int w_ = i >> 6, h0 = i & 63;
        float4 v1 = p1[t4], v3 = p3[t4];
        s1[(h0 + 0) * 65 + w_] = v1.x; s1[(h0 + 1) * 65 + w_] = v1.y;
        s1[(h0 + 2) * 65 + w_] = v1.z; s1[(h0 + 3) * 65 + w_] = v1.w;
        s3[(h0 + 0) * 65 + w_] = v3.x; s3[(h0 + 1) * 65 + w_] = v3.y;
        s3[(h0 + 2) * 65 + w_] = v3.z; s3[(h0 + 3) * 65 + w_] = v3.w;
    }
    __syncthreads();

    float4* po = (float4*)(g_ysum + (size_t)(b * DIN + d) * LSEQ);
    for (int t4 = tid; t4 < 1024; t4 += 256) {
        int j = t4 * 4;
        int h = j >> 6, w0 = j & 63;
        float4 a = p0[t4], c = p2[t4];
        float4 r;
        r.x = a.x + c.x + s1[h * 65 + w0 + 0] + s3[h * 65 + w0 + 0];
        r.y = a.y + c.y + s1[h * 65 + w0 + 1] + s3[h * 65 + w0 + 1];
        r.z = a.z + c.z + s1[h * 65 + w0 + 2] + s3[h * 65 + w0 + 2];
        r.w = a.w + c.w + s1[h * 65 + w0 + 3] + s3[h * 65 + w0 + 3];
        po[t4] = r;
    }
}

// ================= K5: out-LN + gate + out_proj + residual =================
__global__ void k5_final(const float* __restrict__ onw, const float* __restrict__ onb,
                         const float* __restrict__ wout, float* __restrict__ out)
{
    extern __shared__ float sm[];
    float* yc = sm;                  // 192*36
    float* ws = sm + 192 * 36;       // 96*192
    const int tid = threadIdx.x, lane = tid & 31, warp = tid >> 5;
    const int b = blockIdx.x >> 7;
    const int l0 = (blockIdx.x & 127) << 5;

    for (int i = tid; i < 192 * 32; i += 256) {
        int d = i >> 5, p = i & 31;
        yc[d * 36 + p] = g_ysum[(size_t)(b * DIN + d) * LSEQ + l0 + p];
    }
    for (int i = tid; i < 96 * 192; i += 256) ws[i] = wout[i];
    __syncthreads();

    #pragma unroll
    for (int pp = 0; pp < 4; pp++) {
        const int p = warp * 4 + pp;
        float s = 0.f, s2 = 0.f, vv[6];
        #pragma unroll
        for (int j = 0; j < 6; j++) {
            float v = yc[(lane + 32 * j) * 36 + p];
            vv[j] = v; s += v; s2 += v * v;
        }
        #pragma unroll
        for (int o = 16; o > 0; o >>= 1) {
            s  += __shfl_xor_sync(0xffffffffu, s,  o);
            s2 += __shfl_xor_sync(0xffffffffu, s2, o);
        }
        float mu = s * (1.f / 192.f);
        float var = s2 * (1.f / 192.f) - mu * mu;
        float rstd = rsqrtf(var + 1e-5f);
        size_t zbase = ((size_t)(b * LSEQ + l0 + p)) * DIN;
        #pragma unroll
        for (int j = 0; j < 6; j++) {
            int dd = lane + 32 * j;
            float g = (vv[j] - mu) * rstd * onw[dd] + onb[dd];
            yc[dd * 36 + p] = g * g_zs[zbase + dd];
        }
    }
    __syncthreads();

    const int og = tid >> 3;
    const int pg = tid & 7;
    float acc[3][4];
    #pragma unroll
    for (int a = 0; a < 3; a++)
        #pragma unroll
        for (int c = 0; c < 4; c++) acc[a][c] = 0.f;

    #pragma unroll 4
    for (int dd = 0; dd < 192; dd++) {
        float4 gv = *(const float4*)&yc[dd * 36 + pg * 4];
        float g4[4] = {gv.x, gv.y, gv.z, gv.w};
        #pragma unroll
        for (int oi = 0; oi < 3; oi++) {
            float w2 = ws[(og * 3 + oi) * 192 + dd];
            #pragma unroll
            for (int pi = 0; pi < 4; pi++)
                acc[oi][pi] = fmaf(w2, g4[pi], acc[oi][pi]);
        }
    }
    __syncthreads();

    float* buf = sm;                 // 32 x 100 staging
    #pragma unroll
    for (int oi = 0; oi < 3; oi++)
        #pragma unroll
        for (int pi = 0; pi < 4; pi++)
            buf[(pg * 4 + pi) * 100 + og * 3 + oi] = acc[oi][pi];
    __syncthreads();

    const float4* df4 = (const float4*)(g_diff + ((size_t)b * LSEQ + l0) * CDIM);
    float4* out4 = (float4*)(out + ((size_t)b * LSEQ + l0) * CDIM);
    for (int t = tid; t < 32 * 24; t += 256) {
        int p = t / 24, o4 = t % 24;
        float4 v = *(const float4*)&buf[p * 100 + o4 * 4];
        float4 dv = df4[p * 24 + o4];
        v.x += dv.x; v.y += dv.y; v.z += dv.z; v.w += dv.w;
        out4[p * 24 + o4] = v;
    }
}

// ================= launch =================
extern "C" void kernel_launch(void* const* d_in, const int* in_sizes, int n_in,
                              void* d_out, int out_size)
{
    const float* x     = (const float*)d_in[0];
    const float* y     = (const float*)d_in[1];
    const float* ln_w  = (const float*)d_in[2];
    const float* ln_b  = (const float*)d_in[3];
    const float* ipw   = (const float*)d_in[4];
    const float* cw    = (const float*)d_in[5];
    const float* cb    = (const float*)d_in[6];
    const float* xpw   = (const float*)d_in[7];
    const float* dtw   = (const float*)d_in[8];
    const float* dtb   = (const float*)d_in[9];
    const float* alog  = (const float*)d_in[10];
    const float* ds    = (const float*)d_in[11];
    const float* onw   = (const float*)d_in[12];
    const float* onb   = (const float*)d_in[13];
    const float* wout  = (const float*)d_in[14];
    float* out = (float*)d_out;

    const int smem1 = (96 * 64 + 96 * 128) * 4;
    const int smem3 = (192 * 64 + 192 * 48 + 38 * 65 + 192 * 6 + 192) * 4;
    const int smem5 = (192 * 36 + 96 * 192) * 4;
    cudaFuncSetAttribute(k1_prologue, cudaFuncAttributeMaxDynamicSharedMemorySize, smem1);
    cudaFuncSetAttribute(k3_xproj,   cudaFuncAttributeMaxDynamicSharedMemorySize, smem3);
    cudaFuncSetAttribute(k5_final,   cudaFuncAttributeMaxDynamicSharedMemorySize, smem5);

    k1_prologue<<<dim3(128, 3), 256, smem1>>>(x, y, ln_w, ln_b, ipw);
    k2_conv<<<BATCH * DIN, 256>>>(cw, cb);
    k3_xproj<<<BATCH * 4 * (LSEQ / 64), 256, smem3>>>(xpw, dtw, dtb);
    k4a_scan<<<dim3(768, 2), 256>>>(alog);
    k4b_carry<<<NCH * NST / 256, 256>>>();
    k4c_scan<<<dim3(384, 2), 256>>>(alog, ds);
    k4t_merge<<<BATCH * DIN, 256>>>();
    k5_final<<<BATCH * (LSEQ / 32), 256, smem5>>>(onw, onb, wout, out);
}